// round 13
// baseline (speedup 1.0000x reference)
#include <cuda_runtime.h>
#include <cuda_fp16.h>
#include <math.h>
#include <stdint.h>

// Problem constants
#define BB   32
#define IDF_ 512
#define CDF_ 512
#define QQ   4096   // 64*64
#define LL   256

#define WC_ELEMS ((size_t)BB * IDF_ * QQ)

// ---------------------------------------------------------------------------
// Scratch (static device memory; no allocation at runtime)
// ---------------------------------------------------------------------------
__device__ float  g_source [(size_t)BB * IDF_ * LL];   // [b][i][l] fp32
__device__ float  g_text   [(size_t)BB * IDF_ * LL];   // [b][i][l] fp32
__device__ float  g_attn   [(size_t)BB * QQ  * LL];    // [b][q][l] fp32 (exp(p))
__device__ float  g_combine[(size_t)BB * QQ  * LL];    // [b][q][l] fp32
__device__ float  g_partial[BB * 16 * LL];
__device__ float  g_rsums  [BB * LL];
// fp16 hi/lo pre-split operands
__device__ __half g_xT_h  [(size_t)BB * QQ * IDF_];    // [b][q][i]
__device__ __half g_xT_l  [(size_t)BB * QQ * IDF_];
__device__ __half g_imgT_h[(size_t)BB * QQ * IDF_];    // [b][q][o]
__device__ __half g_imgT_l[(size_t)BB * QQ * IDF_];
__device__ __half g_w_h   [IDF_ * CDF_];               // w_img [o][i]
__device__ __half g_w_l   [IDF_ * CDF_];
__device__ __half g_wc_h  [IDF_ * CDF_];               // w_context [o][c]
__device__ __half g_wc_l  [IDF_ * CDF_];
__device__ __half g_wt_h  [IDF_ * CDF_];               // w_text [o][c]
__device__ __half g_wt_l  [IDF_ * CDF_];
__device__ __half g_ctxT_h[(size_t)BB * LL * CDF_];    // [b][l][c]
__device__ __half g_ctxT_l[(size_t)BB * LL * CDF_];
__device__ __half g_srcT_h[(size_t)BB * LL * IDF_];    // [b][l][i]
__device__ __half g_srcT_l[(size_t)BB * LL * IDF_];
__device__ __half g_txtT_h[(size_t)BB * LL * IDF_];    // [b][l][i]
__device__ __half g_txtT_l[(size_t)BB * LL * IDF_];
__device__ __half g_src_h [(size_t)BB * IDF_ * LL];    // [b][i][l]
__device__ __half g_src_l [(size_t)BB * IDF_ * LL];
__device__ __half g_am_h  [(size_t)BB * QQ * LL];      // [b][q][l]
__device__ __half g_am_l  [(size_t)BB * QQ * LL];

// ---------------------------------------------------------------------------
// Helpers
// ---------------------------------------------------------------------------
__device__ __forceinline__ void split_f16(float v, __half& h, __half& l) {
    h = __float2half_rn(v);
    l = __float2half_rn(v - __half2float(h));
}
__device__ __forceinline__ void split2_f16(float v0, float v1,
                                           uint32_t& hi, uint32_t& lo) {
    __half2 h = __floats2half2_rn(v0, v1);
    float2 hf = __half22float2(h);
    __half2 l = __floats2half2_rn(v0 - hf.x, v1 - hf.y);
    hi = *(uint32_t*)&h;
    lo = *(uint32_t*)&l;
}
__device__ __forceinline__ void mma_f16(float* c, const uint32_t* a, const uint32_t* b) {
    asm volatile(
        "mma.sync.aligned.m16n8k16.row.col.f32.f16.f16.f32 "
        "{%0,%1,%2,%3}, {%4,%5,%6,%7}, {%8,%9}, {%0,%1,%2,%3};"
        : "+f"(c[0]), "+f"(c[1]), "+f"(c[2]), "+f"(c[3])
        : "r"(a[0]), "r"(a[1]), "r"(a[2]), "r"(a[3]), "r"(b[0]), "r"(b[1]));
}
__device__ __forceinline__ void cp_async16(uint32_t smem_dst, const void* gsrc) {
    asm volatile("cp.async.cg.shared.global [%0], [%1], 16;"
                 :: "r"(smem_dst), "l"(gsrc) : "memory");
}
#define CP_COMMIT() asm volatile("cp.async.commit_group;" ::: "memory")
#define CP_WAIT(n)  asm volatile("cp.async.wait_group %0;" :: "n"(n) : "memory")
#define LDSM4(r0, r1, r2, r3, addr) \
    asm volatile("ldmatrix.sync.aligned.m8n8.x4.shared.b16 {%0,%1,%2,%3}, [%4];" \
                 : "=r"(r0), "=r"(r1), "=r"(r2), "=r"(r3) : "r"(addr))

// ---------------------------------------------------------------------------
// Pure-fp16 hi/lo GEMM (3xFP16 Markidis, fp32-equivalent):
//   C[M,N] = A * B^T,  A = Ah+Al [M][K] fp16 rm,  B = Bh+Bl [N][K] fp16 rm.
// EPI: 0 = fp32 C; 1 = tanh fp32 C; 2 = tanh + split to Ch/Cl fp16;
//      3 = fp32 C AND split to Ch/Cl fp16.
// Block tile 128x256, warp tile 64x64 (8 warps 2x4), 1 CTA/SM.
// K-chunk 32, 3-stage cp.async ring (one __syncthreads per 32-K).
// Smem per buffer: row r x 64B; 16B quarter qd at r*64+16*(qd^((r>>1)&3)).
// ---------------------------------------------------------------------------
#define STG_B  49152    // Ah 8K | Al 8K | Bh 16K | Bl 16K
#define HG_SMEM (3 * STG_B)

template <int EPI>
__global__ __launch_bounds__(256, 1) void hgemm_kernel(
    const __half* __restrict__ Ahb, const __half* __restrict__ Alb,
    const __half* __restrict__ Bhb, const __half* __restrict__ Blb,
    float* __restrict__ Cb, __half* __restrict__ Chb, __half* __restrict__ Clb,
    int M, int N, int K,
    long long sA, long long sB, long long sC)
{
    extern __shared__ __align__(16) char dsm[];
    const uint32_t base = (uint32_t)__cvta_generic_to_shared(dsm);

    const __half* Ah = Ahb + (size_t)blockIdx.z * sA;
    const __half* Al = Alb + (size_t)blockIdx.z * sA;
    const __half* Bh = Bhb + (size_t)blockIdx.z * sB;
    const __half* Bl = Blb + (size_t)blockIdx.z * sB;

    const int tid  = threadIdx.x;
    const int lane = tid & 31;
    const int wid  = tid >> 5;
    const int m0   = blockIdx.y * 128;
    const int n0   = blockIdx.x * 256;
    const int wm   = (wid & 1) * 64;
    const int wn   = (wid >> 1) * 64;
    const int qr   = lane >> 2;
    const int tc   = lane & 3;
    const int rl   = lane & 15;
    const int khl  = lane >> 4;

    float acc[4][8][4];
#pragma unroll
    for (int i = 0; i < 4; i++)
#pragma unroll
        for (int j = 0; j < 8; j++)
#pragma unroll
            for (int v = 0; v < 4; v++) acc[i][j][v] = 0.f;

    // A staging: thread -> row (tid>>1), two quarters
    const int sa_r = tid >> 1;
    const int sa_q = (tid & 1) * 2;
    const uint32_t sa_d0 = sa_r * 64 + 16 * ((sa_q)     ^ ((sa_r >> 1) & 3));
    const uint32_t sa_d1 = sa_r * 64 + 16 * ((sa_q + 1) ^ ((sa_r >> 1) & 3));
    // B staging: thread -> row tid, all 4 quarters
    uint32_t sb_d[4];
#pragma unroll
    for (int j = 0; j < 4; j++) sb_d[j] = tid * 64 + 16 * (j ^ ((tid >> 1) & 3));

    auto issue_chunk = [&](int k0, int s) {
        const uint32_t sbb = base + s * STG_B;
        const size_t ao = (size_t)(m0 + sa_r) * K + k0 + sa_q * 8;
        cp_async16(sbb + sa_d0,        Ah + ao);
        cp_async16(sbb + sa_d1,        Ah + ao + 8);
        cp_async16(sbb + 8192 + sa_d0, Al + ao);
        cp_async16(sbb + 8192 + sa_d1, Al + ao + 8);
        const size_t bo = (size_t)(n0 + tid) * K + k0;
#pragma unroll
        for (int j = 0; j < 4; j++) {
            cp_async16(sbb + 16384 + sb_d[j], Bh + bo + j * 8);
            cp_async16(sbb + 32768 + sb_d[j], Bl + bo + j * 8);
        }
        CP_COMMIT();
    };

    auto mma_chunk = [&](int c) {
        const uint32_t sbb = base + (c % 3) * STG_B;
#pragma unroll
        for (int ks = 0; ks < 2; ks++) {
            const int qd = 2 * ks + khl;
            uint32_t bh[8][2], bl[8][2];
#pragma unroll
            for (int nip = 0; nip < 4; nip++) {
                int n = wn + 16 * nip + rl;
                uint32_t off = n * 64 + 16 * (qd ^ ((n >> 1) & 3));
                uint32_t t0, t1, t2, t3;
                LDSM4(t0, t1, t2, t3, sbb + 16384 + off);
                bh[2 * nip][0] = t0; bh[2 * nip + 1][0] = t1;
                bh[2 * nip][1] = t2; bh[2 * nip + 1][1] = t3;
                LDSM4(t0, t1, t2, t3, sbb + 32768 + off);
                bl[2 * nip][0] = t0; bl[2 * nip + 1][0] = t1;
                bl[2 * nip][1] = t2; bl[2 * nip + 1][1] = t3;
            }
#pragma unroll
            for (int mi = 0; mi < 4; mi++) {
                int r = wm + 16 * mi + rl;
                uint32_t off = r * 64 + 16 * (qd ^ ((r >> 1) & 3));
                uint32_t ah[4], al[4];
                LDSM4(ah[0], ah[1], ah[2], ah[3], sbb + off);
                LDSM4(al[0], al[1], al[2], al[3], sbb + 8192 + off);
#pragma unroll
                for (int ni = 0; ni < 8; ni++) mma_f16(acc[mi][ni], ah, bh[ni]);
#pragma unroll
                for (int ni = 0; ni < 8; ni++) mma_f16(acc[mi][ni], ah, bl[ni]);
#pragma unroll
                for (int ni = 0; ni < 8; ni++) mma_f16(acc[mi][ni], al, bh[ni]);
            }
        }
    };

    const int nchunk = K >> 5;
    issue_chunk(0, 0);
    issue_chunk(32, 1);

    for (int c = 0; c < nchunk; c++) {
        if (c + 1 < nchunk) CP_WAIT(1); else CP_WAIT(0);
        __syncthreads();
        if (c + 2 < nchunk) issue_chunk((c + 2) << 5, (c + 2) % 3);
        mma_chunk(c);
    }

    // ---- epilogue ----
#pragma unroll
    for (int mi = 0; mi < 4; mi++) {
#pragma unroll
        for (int ni = 0; ni < 8; ni++) {
            int r0  = m0 + wm + 16 * mi + qr;
            int col = n0 + wn + 8 * ni + 2 * tc;
            float c0 = acc[mi][ni][0], c1 = acc[mi][ni][1];
            float c2 = acc[mi][ni][2], c3 = acc[mi][ni][3];
            if (EPI == 1 || EPI == 2) {
                c0 = tanhf(c0); c1 = tanhf(c1); c2 = tanhf(c2); c3 = tanhf(c3);
            }
            if (EPI == 2 || EPI == 3) {
                __half* Ch = Chb + (size_t)blockIdx.z * sC;
                __half* Cl = Clb + (size_t)blockIdx.z * sC;
                uint32_t H, L;
                split2_f16(c0, c1, H, L);
                *(uint32_t*)&Ch[(size_t)r0 * N + col] = H;
                *(uint32_t*)&Cl[(size_t)r0 * N + col] = L;
                split2_f16(c2, c3, H, L);
                *(uint32_t*)&Ch[(size_t)(r0 + 8) * N + col] = H;
                *(uint32_t*)&Cl[(size_t)(r0 + 8) * N + col] = L;
            }
            if (EPI != 2) {
                float* C = Cb + (size_t)blockIdx.z * sC;
                *(float2*)(C + (size_t)r0 * N + col)       = make_float2(c0, c1);
                *(float2*)(C + (size_t)(r0 + 8) * N + col) = make_float2(c2, c3);
            }
        }
    }
}

// ---------------------------------------------------------------------------
// Transpose + split: in fp32 [z][R][C] -> oh/ol fp16 [z][C][R] (half2 stores).
// ---------------------------------------------------------------------------
__global__ __launch_bounds__(256) void split_tr_kernel(
    const float* __restrict__ in, __half* __restrict__ oh, __half* __restrict__ ol,
    int R, int C)
{
    const size_t zo = (size_t)blockIdx.z * R * C;
    const int r0 = blockIdx.y * 32, c0 = blockIdx.x * 32;
    const int tx = threadIdx.x, ty = threadIdx.y;
    const int tid = ty * 32 + tx;
    __shared__ float t[32][33];
#pragma unroll
    for (int i = 0; i < 4; i++)
        t[ty + 8 * i][tx] = in[zo + (size_t)(r0 + ty + 8 * i) * C + c0 + tx];
    __syncthreads();
    const int op = tid & 15;
#pragma unroll
    for (int j = 0; j < 2; j++) {
        int oc = (tid >> 4) + 16 * j;
        float v0 = t[2 * op][oc], v1 = t[2 * op + 1][oc];
        __half2 h = __floats2half2_rn(v0, v1);
        float2 hf = __half22float2(h);
        __half2 l = __floats2half2_rn(v0 - hf.x, v1 - hf.y);
        size_t o = zo + (size_t)(c0 + oc) * R + r0 + 2 * op;
        *(__half2*)(oh + o) = h;
        *(__half2*)(ol + o) = l;
    }
}

// Plain elementwise split: fp32[2*n2] -> h/l fp16.
__global__ __launch_bounds__(256) void split_plain_kernel(
    const float* __restrict__ in, __half* __restrict__ oh, __half* __restrict__ ol,
    size_t n2)
{
    size_t i = (size_t)blockIdx.x * 256 + threadIdx.x;
    if (i < n2) {
        float2 v = *(const float2*)(in + 2 * i);
        __half2 h = __floats2half2_rn(v.x, v.y);
        float2 hf = __half22float2(h);
        __half2 l = __floats2half2_rn(v.x - hf.x, v.y - hf.y);
        *(__half2*)(oh + 2 * i) = h;
        *(__half2*)(ol + 2 * i) = l;
    }
}

// ---------------------------------------------------------------------------
// Softmax over L=256 in place; stores exp(p) (p = softmax prob). One block/row.
// ---------------------------------------------------------------------------
__global__ __launch_bounds__(256) void softmax_rows256(float* __restrict__ data)
{
    const size_t row = blockIdx.x;
    const int t = threadIdx.x;
    float v = data[row * LL + t];

    __shared__ float red[8];
    float m = v;
#pragma unroll
    for (int o = 16; o; o >>= 1) m = fmaxf(m, __shfl_xor_sync(0xffffffffu, m, o));
    if ((t & 31) == 0) red[t >> 5] = m;
    __syncthreads();
    if (t < 8) {
        float x = red[t];
#pragma unroll
        for (int o = 4; o; o >>= 1) x = fmaxf(x, __shfl_xor_sync(0xffu, x, o));
        if (t == 0) red[0] = x;
    }
    __syncthreads();
    m = red[0];
    float e = expf(v - m);
    __syncthreads();
    float s = e;
#pragma unroll
    for (int o = 16; o; o >>= 1) s += __shfl_xor_sync(0xffffffffu, s, o);
    if ((t & 31) == 0) red[t >> 5] = s;
    __syncthreads();
    if (t < 8) {
        float x = red[t];
#pragma unroll
        for (int o = 4; o; o >>= 1) x += __shfl_xor_sync(0xffu, x, o);
        if (t == 0) red[0] = x;
    }
    __syncthreads();
    data[row * LL + t] = expf(e / red[0]);   // store exp(p)
}

// ---------------------------------------------------------------------------
// Second softmax (over Q): g_attn already holds exp(p) -> plain sums.
// ---------------------------------------------------------------------------
__global__ __launch_bounds__(256) void sumexp_partial_kernel()
{
    const int b = blockIdx.x;
    const int chunk = blockIdx.y;
    const int l = threadIdx.x;
    const size_t base = ((size_t)b * QQ + (size_t)chunk * 256) * LL + l;
    float s = 0.f;
#pragma unroll 8
    for (int q = 0; q < 256; q++) s += g_attn[base + (size_t)q * LL];
    g_partial[(b * 16 + chunk) * LL + l] = s;
}

__global__ __launch_bounds__(256) void sumexp_reduce_kernel()
{
    const int b = blockIdx.x;
    const int l = threadIdx.x;
    float s = 0.f;
#pragma unroll
    for (int c = 0; c < 16; c++) s += g_partial[(b * 16 + c) * LL + l];
    g_rsums[b * LL + l] = 1.0f / s;
}

// ---------------------------------------------------------------------------
// Finalize: v = stored_exp * rsum * combine; out_am fp32 [b][l][q] + am h/l.
// ---------------------------------------------------------------------------
__global__ __launch_bounds__(256) void finalize_kernel(float* __restrict__ out_am)
{
    const int b  = blockIdx.y;
    const int q0 = blockIdx.x * 32;
    const int tx = threadIdx.x;
    const int ty = threadIdx.y;

    __shared__ float tile[32][33];

    for (int l0 = 0; l0 < LL; l0 += 32) {
        const float rs_col = g_rsums[b * LL + l0 + tx];
#pragma unroll
        for (int r = 0; r < 4; r++) {
            const int q = q0 + ty + 8 * r;
            const size_t idx = ((size_t)b * QQ + q) * LL + l0 + tx;
            float v = g_attn[idx] * rs_col * g_combine[idx];
            tile[ty + 8 * r][tx] = v;
            __half h, l;
            split_f16(v, h, l);
            g_am_h[idx] = h;
            g_am_l[idx] = l;
        }
        __syncthreads();
#pragma unroll
        for (int r = 0; r < 4; r++) {
            const int l = l0 + ty + 8 * r;
            out_am[((size_t)b * LL + l) * QQ + q0 + tx] = tile[tx][ty + 8 * r];
        }
        __syncthreads();
    }
}

// ---------------------------------------------------------------------------
// Launcher
// ---------------------------------------------------------------------------
extern "C" void kernel_launch(void* const* d_in, const int* in_sizes, int n_in,
                              void* d_out, int out_size)
{
    const float* x         = (const float*)d_in[0];
    const float* context   = (const float*)d_in[1];
    const float* w_context = (const float*)d_in[2];
    const float* w_img     = (const float*)d_in[3];
    const float* w_text    = (const float*)d_in[4];

    float* out_wc = (float*)d_out;
    float* out_am = out_wc + WC_ELEMS;

    float *p_source, *p_text, *p_attn, *p_combine;
    cudaGetSymbolAddress((void**)&p_source,  g_source);
    cudaGetSymbolAddress((void**)&p_text,    g_text);
    cudaGetSymbolAddress((void**)&p_attn,    g_attn);
    cudaGetSymbolAddress((void**)&p_combine, g_combine);
    __half *xh, *xl, *ih, *il, *wh, *wl, *wch, *wcl, *wth, *wtl;
    __half *cth, *ctl, *sth, *stl, *tth, *ttl, *sh, *sl, *amh, *aml;
    cudaGetSymbolAddress((void**)&xh,  g_xT_h);   cudaGetSymbolAddress((void**)&xl,  g_xT_l);
    cudaGetSymbolAddress((void**)&ih,  g_imgT_h); cudaGetSymbolAddress((void**)&il,  g_imgT_l);
    cudaGetSymbolAddress((void**)&wh,  g_w_h);    cudaGetSymbolAddress((void**)&wl,  g_w_l);
    cudaGetSymbolAddress((void**)&wch, g_wc_h);   cudaGetSymbolAddress((void**)&wcl, g_wc_l);
    cudaGetSymbolAddress((void**)&wth, g_wt_h);   cudaGetSymbolAddress((void**)&wtl, g_wt_l);
    cudaGetSymbolAddress((void**)&cth, g_ctxT_h); cudaGetSymbolAddress((void**)&ctl, g_ctxT_l);
    cudaGetSymbolAddress((void**)&sth, g_srcT_h); cudaGetSymbolAddress((void**)&stl, g_srcT_l);
    cudaGetSymbolAddress((void**)&tth, g_txtT_h); cudaGetSymbolAddress((void**)&ttl, g_txtT_l);
    cudaGetSymbolAddress((void**)&sh,  g_src_h);  cudaGetSymbolAddress((void**)&sl,  g_src_l);
    cudaGetSymbolAddress((void**)&amh, g_am_h);   cudaGetSymbolAddress((void**)&aml, g_am_l);

    cudaFuncSetAttribute(hgemm_kernel<0>, cudaFuncAttributeMaxDynamicSharedMemorySize, HG_SMEM);
    cudaFuncSetAttribute(hgemm_kernel<1>, cudaFuncAttributeMaxDynamicSharedMemorySize, HG_SMEM);
    cudaFuncSetAttribute(hgemm_kernel<2>, cudaFuncAttributeMaxDynamicSharedMemorySize, HG_SMEM);
    cudaFuncSetAttribute(hgemm_kernel<3>, cudaFuncAttributeMaxDynamicSharedMemorySize, HG_SMEM);

    const long long sSL  = (long long)IDF_ * LL;
    const long long sQI  = (long long)QQ * IDF_;
    const long long sLI  = (long long)LL * IDF_;
    const long long sLC  = (long long)LL * CDF_;
    const long long sQL  = (long long)QQ * LL;
    const long long sIQ  = (long long)IDF_ * QQ;

    // 1) ctxT split: context [b][c][l] -> [b][l][c] h/l
    split_tr_kernel<<<dim3(LL / 32, CDF_ / 32, BB), dim3(32, 8)>>>(context, cth, ctl, CDF_, LL);
    // 2-3) weight splits
    split_plain_kernel<<<(IDF_ * CDF_ / 2 + 255) / 256, 256>>>(w_context, wch, wcl, IDF_ * CDF_ / 2);
    split_plain_kernel<<<(IDF_ * CDF_ / 2 + 255) / 256, 256>>>(w_text, wth, wtl, IDF_ * CDF_ / 2);
    // 4) source = wc @ ctxT^T -> fp32 [b][i][l] AND h/l  (PROFILED launch)
    hgemm_kernel<3><<<dim3(1, 4, BB), 256, HG_SMEM>>>(
        wch, wcl, cth, ctl, p_source, sh, sl, IDF_, LL, CDF_, 0, sLC, sSL);
    // 5) xT split: x [b][i][q] -> [b][q][i] h/l
    split_tr_kernel<<<dim3(QQ / 32, IDF_ / 32, BB), dim3(32, 8)>>>(x, xh, xl, IDF_, QQ);
    // 6) text = tanh(wt @ ctxT^T) -> fp32 [b][i][l]
    hgemm_kernel<1><<<dim3(1, 4, BB), 256, HG_SMEM>>>(
        wth, wtl, cth, ctl, p_text, nullptr, nullptr, IDF_, LL, CDF_, 0, sLC, sSL);
    // 7-8) srcT / txtT splits
    split_tr_kernel<<<dim3(LL / 32, IDF_ / 32, BB), dim3(32, 8)>>>(p_source, sth, stl, IDF_, LL);
    split_tr_kernel<<<dim3(LL / 32, IDF_ / 32, BB), dim3(32, 8)>>>(p_text, tth, ttl, IDF_, LL);
    // 9) w_img split
    split_plain_kernel<<<(IDF_ * CDF_ / 2 + 255) / 256, 256>>>(w_img, wh, wl, IDF_ * CDF_ / 2);
    // 10) attn = xT @ srcT^T -> fp32 [b][q][l]
    hgemm_kernel<0><<<dim3(1, 32, BB), 256, HG_SMEM>>>(
        xh, xl, sth, stl, p_attn, nullptr, nullptr, QQ, LL, IDF_, sQI, sLI, sQL);
    // 11) imgT = tanh(xT @ w^T) -> h/l [b][q][o]
    hgemm_kernel<2><<<dim3(2, 32, BB), 256, HG_SMEM>>>(
        xh, xl, wh, wl, nullptr, ih, il, QQ, IDF_, IDF_, sQI, 0, sQI);
    // 12) combine = tanh(imgT @ txtT^T) -> fp32 [b][q][l]
    hgemm_kernel<1><<<dim3(1, 32, BB), 256, HG_SMEM>>>(
        ih, il, tth, ttl, p_combine, nullptr, nullptr, QQ, LL, IDF_, sQI, sLI, sQL);
    // 13-15) softmax (stores exp(p)); second softmax sums
    softmax_rows256<<<BB * QQ, 256>>>(p_attn);
    sumexp_partial_kernel<<<dim3(BB, 16), 256>>>();
    sumexp_reduce_kernel<<<BB, 256>>>();
    // 16) finalize -> out_am fp32 [b][l][q] + am h/l [b][q][l]
    finalize_kernel<<<dim3(QQ / 32, BB), dim3(32, 8)>>>(out_am);
    // 17) wc = source @ am^T -> fp32 [b][i][q]
    hgemm_kernel<0><<<dim3(16, 4, BB), 256, HG_SMEM>>>(
        sh, sl, amh, aml, out_wc, nullptr, nullptr, IDF_, QQ, LL, sSL, sQL, sIQ);
}

// round 14
// speedup vs baseline: 1.3102x; 1.3102x over previous
#include <cuda_runtime.h>
#include <cuda_fp16.h>
#include <math.h>
#include <stdint.h>

// Problem constants
#define BB   32
#define IDF_ 512
#define CDF_ 512
#define QQ   4096   // 64*64
#define LL   256

#define WC_ELEMS ((size_t)BB * IDF_ * QQ)

// ---------------------------------------------------------------------------
// Scratch (static device memory; no allocation at runtime)
// ---------------------------------------------------------------------------
__device__ float  g_source [(size_t)BB * IDF_ * LL];   // [b][i][l] fp32
__device__ float  g_text   [(size_t)BB * IDF_ * LL];   // [b][i][l] fp32
__device__ float  g_attn   [(size_t)BB * QQ  * LL];    // [b][q][l] fp32 (exp(p))
__device__ float  g_combine[(size_t)BB * QQ  * LL];    // [b][q][l] fp32 (gated v)
__device__ float  g_partial[BB * 16 * LL];
__device__ float  g_rsums  [BB * LL];
// fp16 hi/lo pre-split operands
__device__ __half g_xT_h  [(size_t)BB * QQ * IDF_];    // [b][q][i]
__device__ __half g_xT_l  [(size_t)BB * QQ * IDF_];
__device__ __half g_imgT_h[(size_t)BB * QQ * IDF_];    // [b][q][o]
__device__ __half g_imgT_l[(size_t)BB * QQ * IDF_];
__device__ __half g_w_h   [IDF_ * CDF_];               // w_img [o][i]
__device__ __half g_w_l   [IDF_ * CDF_];
__device__ __half g_wc_h  [IDF_ * CDF_];               // w_context [o][c]
__device__ __half g_wc_l  [IDF_ * CDF_];
__device__ __half g_wt_h  [IDF_ * CDF_];               // w_text [o][c]
__device__ __half g_wt_l  [IDF_ * CDF_];
__device__ __half g_ctxT_h[(size_t)BB * LL * CDF_];    // [b][l][c]
__device__ __half g_ctxT_l[(size_t)BB * LL * CDF_];
__device__ __half g_srcT_h[(size_t)BB * LL * IDF_];    // [b][l][i]
__device__ __half g_srcT_l[(size_t)BB * LL * IDF_];
__device__ __half g_txtT_h[(size_t)BB * LL * IDF_];    // [b][l][i]
__device__ __half g_txtT_l[(size_t)BB * LL * IDF_];
__device__ __half g_src_h [(size_t)BB * IDF_ * LL];    // [b][i][l]
__device__ __half g_src_l [(size_t)BB * IDF_ * LL];
__device__ __half g_am_h  [(size_t)BB * QQ * LL];      // [b][q][l]
__device__ __half g_am_l  [(size_t)BB * QQ * LL];

// ---------------------------------------------------------------------------
// Helpers
// ---------------------------------------------------------------------------
__device__ __forceinline__ void split_f16(float v, __half& h, __half& l) {
    h = __float2half_rn(v);
    l = __float2half_rn(v - __half2float(h));
}
__device__ __forceinline__ void split2_f16(float v0, float v1,
                                           uint32_t& hi, uint32_t& lo) {
    __half2 h = __floats2half2_rn(v0, v1);
    float2 hf = __half22float2(h);
    __half2 l = __floats2half2_rn(v0 - hf.x, v1 - hf.y);
    hi = *(uint32_t*)&h;
    lo = *(uint32_t*)&l;
}
__device__ __forceinline__ void mma_f16(float* c, const uint32_t* a, const uint32_t* b) {
    asm volatile(
        "mma.sync.aligned.m16n8k16.row.col.f32.f16.f16.f32 "
        "{%0,%1,%2,%3}, {%4,%5,%6,%7}, {%8,%9}, {%0,%1,%2,%3};"
        : "+f"(c[0]), "+f"(c[1]), "+f"(c[2]), "+f"(c[3])
        : "r"(a[0]), "r"(a[1]), "r"(a[2]), "r"(a[3]), "r"(b[0]), "r"(b[1]));
}
__device__ __forceinline__ void cp_async16(uint32_t smem_dst, const void* gsrc) {
    asm volatile("cp.async.cg.shared.global [%0], [%1], 16;"
                 :: "r"(smem_dst), "l"(gsrc) : "memory");
}
#define CP_COMMIT() asm volatile("cp.async.commit_group;" ::: "memory")
#define CP_WAIT(n)  asm volatile("cp.async.wait_group %0;" :: "n"(n) : "memory")
#define LDSM4(r0, r1, r2, r3, addr) \
    asm volatile("ldmatrix.sync.aligned.m8n8.x4.shared.b16 {%0,%1,%2,%3}, [%4];" \
                 : "=r"(r0), "=r"(r1), "=r"(r2), "=r"(r3) : "r"(addr))

// ---------------------------------------------------------------------------
// Pure-fp16 hi/lo GEMM (3xFP16 Markidis, fp32-equivalent):
//   C[M,N] = A * B^T,  A = Ah+Al [M][K] fp16 rm,  B = Bh+Bl [N][K] fp16 rm.
// EPI: 0 = fp32 C; 1 = tanh fp32 C; 2 = tanh + split to Ch/Cl fp16;
//      3 = fp32 C AND split to Ch/Cl fp16;
//      4 = gated combine: v = tanh(acc)*g_attn*g_rsums, fp32 C + split (N==LL).
// Block tile 128x128, 8 warps (2x4), warp tile 64x32, 2 CTAs/SM (R11 config).
// K-chunk 32, 3-stage cp.async ring (one __syncthreads per 32-K).
// Smem per buffer: row r x 64B; 16B quarter qd at r*64+16*(qd^((r>>1)&3)).
// ---------------------------------------------------------------------------
#define STG_B  32768    // Ah 8K | Al 8K | Bh 8K | Bl 8K
#define HG_SMEM (3 * STG_B)

template <int EPI>
__global__ __launch_bounds__(256, 2) void hgemm_kernel(
    const __half* __restrict__ Ahb, const __half* __restrict__ Alb,
    const __half* __restrict__ Bhb, const __half* __restrict__ Blb,
    float* __restrict__ Cb, __half* __restrict__ Chb, __half* __restrict__ Clb,
    int M, int N, int K,
    long long sA, long long sB, long long sC)
{
    extern __shared__ __align__(16) char dsm[];
    const uint32_t base = (uint32_t)__cvta_generic_to_shared(dsm);

    const __half* Ah = Ahb + (size_t)blockIdx.z * sA;
    const __half* Al = Alb + (size_t)blockIdx.z * sA;
    const __half* Bh = Bhb + (size_t)blockIdx.z * sB;
    const __half* Bl = Blb + (size_t)blockIdx.z * sB;

    const int tid  = threadIdx.x;
    const int lane = tid & 31;
    const int wid  = tid >> 5;
    const int m0   = blockIdx.y * 128;
    const int n0   = blockIdx.x * 128;
    const int wm   = (wid & 1) * 64;
    const int wn   = (wid >> 1) * 32;
    const int qr   = lane >> 2;
    const int tc   = lane & 3;
    const int rl   = lane & 15;
    const int khl  = lane >> 4;

    float acc[4][4][4];
#pragma unroll
    for (int i = 0; i < 4; i++)
#pragma unroll
        for (int j = 0; j < 4; j++)
#pragma unroll
            for (int v = 0; v < 4; v++) acc[i][j][v] = 0.f;

    const int st_r = tid >> 1;
    const int st_q = (tid & 1) * 2;
    const uint32_t st_d0 = st_r * 64 + 16 * ((st_q)     ^ ((st_r >> 1) & 3));
    const uint32_t st_d1 = st_r * 64 + 16 * ((st_q + 1) ^ ((st_r >> 1) & 3));

    auto issue_chunk = [&](int k0, int s) {
        const uint32_t sb = base + s * STG_B;
        const size_t ao = (size_t)(m0 + st_r) * K + k0 + st_q * 8;
        const size_t bo = (size_t)(n0 + st_r) * K + k0 + st_q * 8;
        cp_async16(sb + st_d0,          Ah + ao);
        cp_async16(sb + st_d1,          Ah + ao + 8);
        cp_async16(sb + 8192 + st_d0,   Al + ao);
        cp_async16(sb + 8192 + st_d1,   Al + ao + 8);
        cp_async16(sb + 16384 + st_d0,  Bh + bo);
        cp_async16(sb + 16384 + st_d1,  Bh + bo + 8);
        cp_async16(sb + 24576 + st_d0,  Bl + bo);
        cp_async16(sb + 24576 + st_d1,  Bl + bo + 8);
        CP_COMMIT();
    };

    auto mma_chunk = [&](int c) {
        const uint32_t sb = base + (c % 3) * STG_B;
#pragma unroll
        for (int ks = 0; ks < 2; ks++) {
            const int qd = 2 * ks + khl;
            uint32_t bh[4][2], bl[4][2];
#pragma unroll
            for (int nip = 0; nip < 2; nip++) {
                int n = wn + 16 * nip + rl;
                uint32_t off = n * 64 + 16 * (qd ^ ((n >> 1) & 3));
                uint32_t t0, t1, t2, t3;
                LDSM4(t0, t1, t2, t3, sb + 16384 + off);
                bh[2 * nip][0] = t0; bh[2 * nip + 1][0] = t1;
                bh[2 * nip][1] = t2; bh[2 * nip + 1][1] = t3;
                LDSM4(t0, t1, t2, t3, sb + 24576 + off);
                bl[2 * nip][0] = t0; bl[2 * nip + 1][0] = t1;
                bl[2 * nip][1] = t2; bl[2 * nip + 1][1] = t3;
            }
#pragma unroll
            for (int mi = 0; mi < 4; mi++) {
                int r = wm + 16 * mi + rl;
                uint32_t off = r * 64 + 16 * (qd ^ ((r >> 1) & 3));
                uint32_t ah[4], al[4];
                LDSM4(ah[0], ah[1], ah[2], ah[3], sb + off);
                LDSM4(al[0], al[1], al[2], al[3], sb + 8192 + off);
#pragma unroll
                for (int ni = 0; ni < 4; ni++) {
                    mma_f16(acc[mi][ni], ah, bh[ni]);
                    mma_f16(acc[mi][ni], ah, bl[ni]);
                    mma_f16(acc[mi][ni], al, bh[ni]);
                }
            }
        }
    };

    const int nchunk = K >> 5;   // >= 8 for all calls
    issue_chunk(0, 0);
    issue_chunk(32, 1);

    for (int c = 0; c < nchunk; c++) {
        if (c + 1 < nchunk) CP_WAIT(1); else CP_WAIT(0);
        __syncthreads();
        if (c + 2 < nchunk) issue_chunk((c + 2) << 5, (c + 2) % 3);
        mma_chunk(c);
    }

    // ---- epilogue ----
#pragma unroll
    for (int mi = 0; mi < 4; mi++) {
#pragma unroll
        for (int ni = 0; ni < 4; ni++) {
            int r0  = m0 + wm + 16 * mi + qr;
            int col = n0 + wn + 8 * ni + 2 * tc;
            float c0 = acc[mi][ni][0], c1 = acc[mi][ni][1];
            float c2 = acc[mi][ni][2], c3 = acc[mi][ni][3];
            if (EPI == 1 || EPI == 2 || EPI == 4) {
                c0 = tanhf(c0); c1 = tanhf(c1); c2 = tanhf(c2); c3 = tanhf(c3);
            }
            if (EPI == 4) {
                // gate: v = tanh * exp(p) * rsum   (N == LL, C layout == g_attn)
                const float* At = g_attn + (size_t)blockIdx.z * QQ * LL;
                const float* Rs = g_rsums + blockIdx.z * LL;
                float2 e0 = *(const float2*)&At[(size_t)r0 * N + col];
                float2 e1 = *(const float2*)&At[(size_t)(r0 + 8) * N + col];
                float2 rs = *(const float2*)&Rs[col];
                c0 *= e0.x * rs.x; c1 *= e0.y * rs.y;
                c2 *= e1.x * rs.x; c3 *= e1.y * rs.y;
            }
            if (EPI >= 2) {  // 2,3,4: split h/l
                __half* Ch = Chb + (size_t)blockIdx.z * sC;
                __half* Cl = Clb + (size_t)blockIdx.z * sC;
                uint32_t H, L;
                split2_f16(c0, c1, H, L);
                *(uint32_t*)&Ch[(size_t)r0 * N + col] = H;
                *(uint32_t*)&Cl[(size_t)r0 * N + col] = L;
                split2_f16(c2, c3, H, L);
                *(uint32_t*)&Ch[(size_t)(r0 + 8) * N + col] = H;
                *(uint32_t*)&Cl[(size_t)(r0 + 8) * N + col] = L;
            }
            if (EPI != 2) {  // 0,1,3,4: fp32 C
                float* C = Cb + (size_t)blockIdx.z * sC;
                *(float2*)(C + (size_t)r0 * N + col)       = make_float2(c0, c1);
                *(float2*)(C + (size_t)(r0 + 8) * N + col) = make_float2(c2, c3);
            }
        }
    }
}

// ---------------------------------------------------------------------------
// Transpose + split: in fp32 [z][R][C] -> oh/ol fp16 [z][C][R] (half2 stores).
// ---------------------------------------------------------------------------
__global__ __launch_bounds__(256) void split_tr_kernel(
    const float* __restrict__ in, __half* __restrict__ oh, __half* __restrict__ ol,
    int R, int C)
{
    const size_t zo = (size_t)blockIdx.z * R * C;
    const int r0 = blockIdx.y * 32, c0 = blockIdx.x * 32;
    const int tx = threadIdx.x, ty = threadIdx.y;
    const int tid = ty * 32 + tx;
    __shared__ float t[32][33];
#pragma unroll
    for (int i = 0; i < 4; i++)
        t[ty + 8 * i][tx] = in[zo + (size_t)(r0 + ty + 8 * i) * C + c0 + tx];
    __syncthreads();
    const int op = tid & 15;
#pragma unroll
    for (int j = 0; j < 2; j++) {
        int oc = (tid >> 4) + 16 * j;
        float v0 = t[2 * op][oc], v1 = t[2 * op + 1][oc];
        __half2 h = __floats2half2_rn(v0, v1);
        float2 hf = __half22float2(h);
        __half2 l = __floats2half2_rn(v0 - hf.x, v1 - hf.y);
        size_t o = zo + (size_t)(c0 + oc) * R + r0 + 2 * op;
        *(__half2*)(oh + o) = h;
        *(__half2*)(ol + o) = l;
    }
}

// Plain fp32 transpose: in [z][R][C] -> out [z][C][R].
__global__ __launch_bounds__(256) void transpose_kernel(
    const float* __restrict__ in, float* __restrict__ out, int R, int C)
{
    const size_t zo = (size_t)blockIdx.z * R * C;
    const int r0 = blockIdx.y * 32, c0 = blockIdx.x * 32;
    const int tx = threadIdx.x, ty = threadIdx.y;
    const int tid = ty * 32 + tx;
    __shared__ float t[32][33];
#pragma unroll
    for (int i = 0; i < 4; i++)
        t[ty + 8 * i][tx] = in[zo + (size_t)(r0 + ty + 8 * i) * C + c0 + tx];
    __syncthreads();
    const int op = tid & 15;
#pragma unroll
    for (int j = 0; j < 2; j++) {
        int oc = (tid >> 4) + 16 * j;
        float2 v = make_float2(t[2 * op][oc], t[2 * op + 1][oc]);
        *(float2*)(out + zo + (size_t)(c0 + oc) * R + r0 + 2 * op) = v;
    }
}

// Plain elementwise split: fp32[2*n2] -> h/l fp16.
__global__ __launch_bounds__(256) void split_plain_kernel(
    const float* __restrict__ in, __half* __restrict__ oh, __half* __restrict__ ol,
    size_t n2)
{
    size_t i = (size_t)blockIdx.x * 256 + threadIdx.x;
    if (i < n2) {
        float2 v = *(const float2*)(in + 2 * i);
        __half2 h = __floats2half2_rn(v.x, v.y);
        float2 hf = __half22float2(h);
        __half2 l = __floats2half2_rn(v.x - hf.x, v.y - hf.y);
        *(__half2*)(oh + 2 * i) = h;
        *(__half2*)(ol + 2 * i) = l;
    }
}

// ---------------------------------------------------------------------------
// Softmax over L=256, warp-per-row (8 rows/block); stores exp(p).
// ---------------------------------------------------------------------------
__global__ __launch_bounds__(256) void softmax_rows256(float* __restrict__ data)
{
    const int wid  = threadIdx.x >> 5;
    const int lane = threadIdx.x & 31;
    float* row = data + ((size_t)blockIdx.x * 8 + wid) * LL;

    float4 a = ((float4*)row)[lane];
    float4 b = ((float4*)row)[lane + 32];
    float m = fmaxf(fmaxf(fmaxf(a.x, a.y), fmaxf(a.z, a.w)),
                    fmaxf(fmaxf(b.x, b.y), fmaxf(b.z, b.w)));
#pragma unroll
    for (int o = 16; o; o >>= 1) m = fmaxf(m, __shfl_xor_sync(0xffffffffu, m, o));
    a.x = expf(a.x - m); a.y = expf(a.y - m); a.z = expf(a.z - m); a.w = expf(a.w - m);
    b.x = expf(b.x - m); b.y = expf(b.y - m); b.z = expf(b.z - m); b.w = expf(b.w - m);
    float s = a.x + a.y + a.z + a.w + b.x + b.y + b.z + b.w;
#pragma unroll
    for (int o = 16; o; o >>= 1) s += __shfl_xor_sync(0xffffffffu, s, o);
    const float inv = 1.0f / s;
    a.x = expf(a.x * inv); a.y = expf(a.y * inv); a.z = expf(a.z * inv); a.w = expf(a.w * inv);
    b.x = expf(b.x * inv); b.y = expf(b.y * inv); b.z = expf(b.z * inv); b.w = expf(b.w * inv);
    ((float4*)row)[lane]      = a;
    ((float4*)row)[lane + 32] = b;
}

// ---------------------------------------------------------------------------
// Second softmax (over Q): g_attn holds exp(p) -> plain sums -> reciprocal.
// ---------------------------------------------------------------------------
__global__ __launch_bounds__(256) void sumexp_partial_kernel()
{
    const int b = blockIdx.x;
    const int chunk = blockIdx.y;
    const int l = threadIdx.x;
    const size_t base = ((size_t)b * QQ + (size_t)chunk * 256) * LL + l;
    float s = 0.f;
#pragma unroll 8
    for (int q = 0; q < 256; q++) s += g_attn[base + (size_t)q * LL];
    g_partial[(b * 16 + chunk) * LL + l] = s;
}

__global__ __launch_bounds__(256) void sumexp_reduce_kernel()
{
    const int b = blockIdx.x;
    const int l = threadIdx.x;
    float s = 0.f;
#pragma unroll
    for (int c = 0; c < 16; c++) s += g_partial[(b * 16 + c) * LL + l];
    g_rsums[b * LL + l] = 1.0f / s;
}

// ---------------------------------------------------------------------------
// Launcher
// ---------------------------------------------------------------------------
extern "C" void kernel_launch(void* const* d_in, const int* in_sizes, int n_in,
                              void* d_out, int out_size)
{
    const float* x         = (const float*)d_in[0];
    const float* context   = (const float*)d_in[1];
    const float* w_context = (const float*)d_in[2];
    const float* w_img     = (const float*)d_in[3];
    const float* w_text    = (const float*)d_in[4];

    float* out_wc = (float*)d_out;
    float* out_am = out_wc + WC_ELEMS;

    float *p_source, *p_text, *p_attn, *p_combine;
    cudaGetSymbolAddress((void**)&p_source,  g_source);
    cudaGetSymbolAddress((void**)&p_text,    g_text);
    cudaGetSymbolAddress((void**)&p_attn,    g_attn);
    cudaGetSymbolAddress((void**)&p_combine, g_combine);
    __half *xh, *xl, *ih, *il, *wh, *wl, *wch, *wcl, *wth, *wtl;
    __half *cth, *ctl, *sth, *stl, *tth, *ttl, *sh, *sl, *amh, *aml;
    cudaGetSymbolAddress((void**)&xh,  g_xT_h);   cudaGetSymbolAddress((void**)&xl,  g_xT_l);
    cudaGetSymbolAddress((void**)&ih,  g_imgT_h); cudaGetSymbolAddress((void**)&il,  g_imgT_l);
    cudaGetSymbolAddress((void**)&wh,  g_w_h);    cudaGetSymbolAddress((void**)&wl,  g_w_l);
    cudaGetSymbolAddress((void**)&wch, g_wc_h);   cudaGetSymbolAddress((void**)&wcl, g_wc_l);
    cudaGetSymbolAddress((void**)&wth, g_wt_h);   cudaGetSymbolAddress((void**)&wtl, g_wt_l);
    cudaGetSymbolAddress((void**)&cth, g_ctxT_h); cudaGetSymbolAddress((void**)&ctl, g_ctxT_l);
    cudaGetSymbolAddress((void**)&sth, g_srcT_h); cudaGetSymbolAddress((void**)&stl, g_srcT_l);
    cudaGetSymbolAddress((void**)&tth, g_txtT_h); cudaGetSymbolAddress((void**)&ttl, g_txtT_l);
    cudaGetSymbolAddress((void**)&sh,  g_src_h);  cudaGetSymbolAddress((void**)&sl,  g_src_l);
    cudaGetSymbolAddress((void**)&amh, g_am_h);   cudaGetSymbolAddress((void**)&aml, g_am_l);

    cudaFuncSetAttribute(hgemm_kernel<0>, cudaFuncAttributeMaxDynamicSharedMemorySize, HG_SMEM);
    cudaFuncSetAttribute(hgemm_kernel<1>, cudaFuncAttributeMaxDynamicSharedMemorySize, HG_SMEM);
    cudaFuncSetAttribute(hgemm_kernel<2>, cudaFuncAttributeMaxDynamicSharedMemorySize, HG_SMEM);
    cudaFuncSetAttribute(hgemm_kernel<3>, cudaFuncAttributeMaxDynamicSharedMemorySize, HG_SMEM);
    cudaFuncSetAttribute(hgemm_kernel<4>, cudaFuncAttributeMaxDynamicSharedMemorySize, HG_SMEM);

    const long long sSL  = (long long)IDF_ * LL;
    const long long sQI  = (long long)QQ * IDF_;
    const long long sLI  = (long long)LL * IDF_;
    const long long sLC  = (long long)LL * CDF_;
    const long long sQL  = (long long)QQ * LL;
    const long long sIQ  = (long long)IDF_ * QQ;

    // 1) ctxT split: context [b][c][l] -> [b][l][c] h/l
    split_tr_kernel<<<dim3(LL / 32, CDF_ / 32, BB), dim3(32, 8)>>>(context, cth, ctl, CDF_, LL);
    // 2-3) weight splits
    split_plain_kernel<<<(IDF_ * CDF_ / 2 + 255) / 256, 256>>>(w_context, wch, wcl, IDF_ * CDF_ / 2);
    split_plain_kernel<<<(IDF_ * CDF_ / 2 + 255) / 256, 256>>>(w_text, wth, wtl, IDF_ * CDF_ / 2);
    // 4) source = wc @ ctxT^T -> fp32 [b][i][l] AND h/l  (PROFILED launch)
    hgemm_kernel<3><<<dim3(2, 4, BB), 256, HG_SMEM>>>(
        wch, wcl, cth, ctl, p_source, sh, sl, IDF_, LL, CDF_, 0, sLC, sSL);
    // 5) xT split: x [b][i][q] -> [b][q][i] h/l
    split_tr_kernel<<<dim3(QQ / 32, IDF_ / 32, BB), dim3(32, 8)>>>(x, xh, xl, IDF_, QQ);
    // 6) text = tanh(wt @ ctxT^T) -> fp32 [b][i][l]
    hgemm_kernel<1><<<dim3(2, 4, BB), 256, HG_SMEM>>>(
        wth, wtl, cth, ctl, p_text, nullptr, nullptr, IDF_, LL, CDF_, 0, sLC, sSL);
    // 7-8) srcT / txtT splits
    split_tr_kernel<<<dim3(LL / 32, IDF_ / 32, BB), dim3(32, 8)>>>(p_source, sth, stl, IDF_, LL);
    split_tr_kernel<<<dim3(LL / 32, IDF_ / 32, BB), dim3(32, 8)>>>(p_text, tth, ttl, IDF_, LL);
    // 9) w_img split
    split_plain_kernel<<<(IDF_ * CDF_ / 2 + 255) / 256, 256>>>(w_img, wh, wl, IDF_ * CDF_ / 2);
    // 10) attn = xT @ srcT^T -> fp32 [b][q][l]
    hgemm_kernel<0><<<dim3(2, 32, BB), 256, HG_SMEM>>>(
        xh, xl, sth, stl, p_attn, nullptr, nullptr, QQ, LL, IDF_, sQI, sLI, sQL);
    // 11-13) softmax over L (stores exp(p)); second-softmax sums -> rsums
    softmax_rows256<<<BB * QQ / 8, 256>>>(p_attn);
    sumexp_partial_kernel<<<dim3(BB, 16), 256>>>();
    sumexp_reduce_kernel<<<BB, 256>>>();
    // 14) imgT = tanh(xT @ w^T) -> h/l [b][q][o]
    hgemm_kernel<2><<<dim3(4, 32, BB), 256, HG_SMEM>>>(
        xh, xl, wh, wl, nullptr, ih, il, QQ, IDF_, IDF_, sQI, 0, sQI);
    // 15) combine GATED: v = tanh(imgT@txtT^T) * exp(p) * rsum
    //     -> fp32 g_combine [b][q][l] + am h/l [b][q][l]
    hgemm_kernel<4><<<dim3(2, 32, BB), 256, HG_SMEM>>>(
        ih, il, tth, ttl, p_combine, amh, aml, QQ, LL, IDF_, sQI, sLI, sQL);
    // 16) out_am = transpose(v): [b][q][l] -> [b][l][q]
    transpose_kernel<<<dim3(LL / 32, QQ / 32, BB), dim3(32, 8)>>>(p_combine, out_am, QQ, LL);
    // 17) wc = source @ am^T -> fp32 [b][i][q]
    hgemm_kernel<0><<<dim3(32, 4, BB), 256, HG_SMEM>>>(
        sh, sl, amh, aml, out_wc, nullptr, nullptr, IDF_, QQ, LL, sSL, sQL, sIQ);
}

// round 15
// speedup vs baseline: 1.3863x; 1.0581x over previous
#include <cuda_runtime.h>
#include <cuda_fp16.h>
#include <math.h>
#include <stdint.h>

// Problem constants
#define BB   32
#define IDF_ 512
#define CDF_ 512
#define QQ   4096   // 64*64
#define LL   256

#define WC_ELEMS ((size_t)BB * IDF_ * QQ)

// ---------------------------------------------------------------------------
// Scratch (static device memory; no allocation at runtime)
// ---------------------------------------------------------------------------
__device__ float  g_source [(size_t)BB * IDF_ * LL];   // [b][i][l] fp32
__device__ float  g_text   [(size_t)BB * IDF_ * LL];   // [b][i][l] fp32
__device__ float  g_attn   [(size_t)BB * QQ  * LL];    // [b][q][l] fp32 (exp(p))
__device__ float  g_partial[BB * 16 * LL];
__device__ float  g_rsums  [BB * LL];
// fp16 hi/lo pre-split operands
__device__ __half g_xT_h  [(size_t)BB * QQ * IDF_];    // [b][q][i]
__device__ __half g_xT_l  [(size_t)BB * QQ * IDF_];
__device__ __half g_imgT_h[(size_t)BB * QQ * IDF_];    // [b][q][o]
__device__ __half g_imgT_l[(size_t)BB * QQ * IDF_];
__device__ __half g_w_h   [IDF_ * CDF_];               // w_img [o][i]
__device__ __half g_w_l   [IDF_ * CDF_];
__device__ __half g_wc_h  [IDF_ * CDF_];               // w_context [o][c]
__device__ __half g_wc_l  [IDF_ * CDF_];
__device__ __half g_wt_h  [IDF_ * CDF_];               // w_text [o][c]
__device__ __half g_wt_l  [IDF_ * CDF_];
__device__ __half g_ctxT_h[(size_t)BB * LL * CDF_];    // [b][l][c]
__device__ __half g_ctxT_l[(size_t)BB * LL * CDF_];
__device__ __half g_srcT_h[(size_t)BB * LL * IDF_];    // [b][l][i]
__device__ __half g_srcT_l[(size_t)BB * LL * IDF_];
__device__ __half g_txtT_h[(size_t)BB * LL * IDF_];    // [b][l][i]
__device__ __half g_txtT_l[(size_t)BB * LL * IDF_];
__device__ __half g_src_h [(size_t)BB * IDF_ * LL];    // [b][i][l]
__device__ __half g_src_l [(size_t)BB * IDF_ * LL];
__device__ __half g_am_h  [(size_t)BB * QQ * LL];      // [b][q][l]
__device__ __half g_am_l  [(size_t)BB * QQ * LL];

// ---------------------------------------------------------------------------
// Helpers
// ---------------------------------------------------------------------------
__device__ __forceinline__ void split2_f16(float v0, float v1,
                                           uint32_t& hi, uint32_t& lo) {
    __half2 h = __floats2half2_rn(v0, v1);
    float2 hf = __half22float2(h);
    __half2 l = __floats2half2_rn(v0 - hf.x, v1 - hf.y);
    hi = *(uint32_t*)&h;
    lo = *(uint32_t*)&l;
}
__device__ __forceinline__ void mma_f16(float* c, const uint32_t* a, const uint32_t* b) {
    asm volatile(
        "mma.sync.aligned.m16n8k16.row.col.f32.f16.f16.f32 "
        "{%0,%1,%2,%3}, {%4,%5,%6,%7}, {%8,%9}, {%0,%1,%2,%3};"
        : "+f"(c[0]), "+f"(c[1]), "+f"(c[2]), "+f"(c[3])
        : "r"(a[0]), "r"(a[1]), "r"(a[2]), "r"(a[3]), "r"(b[0]), "r"(b[1]));
}
__device__ __forceinline__ void cp_async16(uint32_t smem_dst, const void* gsrc) {
    asm volatile("cp.async.cg.shared.global [%0], [%1], 16;"
                 :: "r"(smem_dst), "l"(gsrc) : "memory");
}
#define CP_COMMIT() asm volatile("cp.async.commit_group;" ::: "memory")
#define CP_WAIT(n)  asm volatile("cp.async.wait_group %0;" :: "n"(n) : "memory")
#define LDSM4(r0, r1, r2, r3, addr) \
    asm volatile("ldmatrix.sync.aligned.m8n8.x4.shared.b16 {%0,%1,%2,%3}, [%4];" \
                 : "=r"(r0), "=r"(r1), "=r"(r2), "=r"(r3) : "r"(addr))

// ---------------------------------------------------------------------------
// Pure-fp16 hi/lo GEMM (Markidis split, fp32-equivalent at NTERMS=3):
//   C[M,N] = A * B^T,  A = Ah+Al [M][K] fp16 rm,  B = Bh+Bl [N][K] fp16 rm.
// EPI: 0 = fp32 C; 1 = tanh fp32 C; 2 = tanh + split to Ch/Cl fp16;
//      3 = fp32 C AND split to Ch/Cl fp16;
//      5 = gated combine: v = tanh(acc)*g_attn*g_rsums; split h/l to Ch/Cl
//          [q][l] AND write v TRANSPOSED to Cb as [l][q] via smem (N==LL).
// NTERMS: 3 = hh+hl+lh (~2^-22); 2 = hh+hl (~2^-12, for precision-tolerant C).
// Block tile 128x128, 8 warps (2x4), warp tile 64x32, 2 CTAs/SM.
// K-chunk 32, 3-stage cp.async ring. Smem per buffer: row r x 64B,
// 16B quarter qd at r*64+16*(qd^((r>>1)&3)).
// ---------------------------------------------------------------------------
#define STG_B  32768    // Ah 8K | Al 8K | Bh 8K | Bl 8K
#define HG_SMEM (3 * STG_B)

template <int EPI, int NTERMS>
__global__ __launch_bounds__(256, 2) void hgemm_kernel(
    const __half* __restrict__ Ahb, const __half* __restrict__ Alb,
    const __half* __restrict__ Bhb, const __half* __restrict__ Blb,
    float* __restrict__ Cb, __half* __restrict__ Chb, __half* __restrict__ Clb,
    int M, int N, int K,
    long long sA, long long sB, long long sC)
{
    extern __shared__ __align__(16) char dsm[];
    const uint32_t base = (uint32_t)__cvta_generic_to_shared(dsm);

    const __half* Ah = Ahb + (size_t)blockIdx.z * sA;
    const __half* Al = Alb + (size_t)blockIdx.z * sA;
    const __half* Bh = Bhb + (size_t)blockIdx.z * sB;
    const __half* Bl = Blb + (size_t)blockIdx.z * sB;

    const int tid  = threadIdx.x;
    const int lane = tid & 31;
    const int wid  = tid >> 5;
    const int m0   = blockIdx.y * 128;
    const int n0   = blockIdx.x * 128;
    const int wm   = (wid & 1) * 64;
    const int wn   = (wid >> 1) * 32;
    const int qr   = lane >> 2;
    const int tc   = lane & 3;
    const int rl   = lane & 15;
    const int khl  = lane >> 4;

    float acc[4][4][4];
#pragma unroll
    for (int i = 0; i < 4; i++)
#pragma unroll
        for (int j = 0; j < 4; j++)
#pragma unroll
            for (int v = 0; v < 4; v++) acc[i][j][v] = 0.f;

    const int st_r = tid >> 1;
    const int st_q = (tid & 1) * 2;
    const uint32_t st_d0 = st_r * 64 + 16 * ((st_q)     ^ ((st_r >> 1) & 3));
    const uint32_t st_d1 = st_r * 64 + 16 * ((st_q + 1) ^ ((st_r >> 1) & 3));

    auto issue_chunk = [&](int k0, int s) {
        const uint32_t sb = base + s * STG_B;
        const size_t ao = (size_t)(m0 + st_r) * K + k0 + st_q * 8;
        const size_t bo = (size_t)(n0 + st_r) * K + k0 + st_q * 8;
        cp_async16(sb + st_d0,          Ah + ao);
        cp_async16(sb + st_d1,          Ah + ao + 8);
        cp_async16(sb + 8192 + st_d0,   Al + ao);
        cp_async16(sb + 8192 + st_d1,   Al + ao + 8);
        cp_async16(sb + 16384 + st_d0,  Bh + bo);
        cp_async16(sb + 16384 + st_d1,  Bh + bo + 8);
        cp_async16(sb + 24576 + st_d0,  Bl + bo);
        cp_async16(sb + 24576 + st_d1,  Bl + bo + 8);
        CP_COMMIT();
    };

    auto mma_chunk = [&](int c) {
        const uint32_t sb = base + (c % 3) * STG_B;
#pragma unroll
        for (int ks = 0; ks < 2; ks++) {
            const int qd = 2 * ks + khl;
            uint32_t bh[4][2], bl[4][2];
#pragma unroll
            for (int nip = 0; nip < 2; nip++) {
                int n = wn + 16 * nip + rl;
                uint32_t off = n * 64 + 16 * (qd ^ ((n >> 1) & 3));
                uint32_t t0, t1, t2, t3;
                LDSM4(t0, t1, t2, t3, sb + 16384 + off);
                bh[2 * nip][0] = t0; bh[2 * nip + 1][0] = t1;
                bh[2 * nip][1] = t2; bh[2 * nip + 1][1] = t3;
                LDSM4(t0, t1, t2, t3, sb + 24576 + off);
                bl[2 * nip][0] = t0; bl[2 * nip + 1][0] = t1;
                bl[2 * nip][1] = t2; bl[2 * nip + 1][1] = t3;
            }
#pragma unroll
            for (int mi = 0; mi < 4; mi++) {
                int r = wm + 16 * mi + rl;
                uint32_t off = r * 64 + 16 * (qd ^ ((r >> 1) & 3));
                uint32_t ah[4], al[4];
                LDSM4(ah[0], ah[1], ah[2], ah[3], sb + off);
                LDSM4(al[0], al[1], al[2], al[3], sb + 8192 + off);
#pragma unroll
                for (int ni = 0; ni < 4; ni++) {
                    mma_f16(acc[mi][ni], ah, bh[ni]);
                    mma_f16(acc[mi][ni], ah, bl[ni]);
                    if (NTERMS == 3) mma_f16(acc[mi][ni], al, bh[ni]);
                }
            }
        }
    };

    const int nchunk = K >> 5;   // >= 8 for all calls
    issue_chunk(0, 0);
    issue_chunk(32, 1);

    for (int c = 0; c < nchunk; c++) {
        if (c + 1 < nchunk) CP_WAIT(1); else CP_WAIT(0);
        __syncthreads();
        if (c + 2 < nchunk) issue_chunk((c + 2) << 5, (c + 2) % 3);
        mma_chunk(c);
    }

    if (EPI == 5) __syncthreads();   // mainloop smem reads done before reuse
    float* tbuf = (float*)dsm;       // EPI==5: 128l x 128q tile, stride 132

    // ---- epilogue ----
#pragma unroll
    for (int mi = 0; mi < 4; mi++) {
#pragma unroll
        for (int ni = 0; ni < 4; ni++) {
            int r0  = m0 + wm + 16 * mi + qr;
            int col = n0 + wn + 8 * ni + 2 * tc;
            float c0 = acc[mi][ni][0], c1 = acc[mi][ni][1];
            float c2 = acc[mi][ni][2], c3 = acc[mi][ni][3];
            if (EPI == 1 || EPI == 2 || EPI == 5) {
                c0 = tanhf(c0); c1 = tanhf(c1); c2 = tanhf(c2); c3 = tanhf(c3);
            }
            if (EPI == 5) {
                // gate: v = tanh * exp(p) * rsum   (N == LL, layout == g_attn)
                const float* At = g_attn + (size_t)blockIdx.z * QQ * LL;
                const float* Rs = g_rsums + blockIdx.z * LL;
                float2 e0 = *(const float2*)&At[(size_t)r0 * N + col];
                float2 e1 = *(const float2*)&At[(size_t)(r0 + 8) * N + col];
                float2 rs = *(const float2*)&Rs[col];
                c0 *= e0.x * rs.x; c1 *= e0.y * rs.y;
                c2 *= e1.x * rs.x; c3 *= e1.y * rs.y;
            }
            if (EPI >= 2) {  // 2,3,5: split h/l
                __half* Ch = Chb + (size_t)blockIdx.z * sC;
                __half* Cl = Clb + (size_t)blockIdx.z * sC;
                uint32_t H, L;
                split2_f16(c0, c1, H, L);
                *(uint32_t*)&Ch[(size_t)r0 * N + col] = H;
                *(uint32_t*)&Cl[(size_t)r0 * N + col] = L;
                split2_f16(c2, c3, H, L);
                *(uint32_t*)&Ch[(size_t)(r0 + 8) * N + col] = H;
                *(uint32_t*)&Cl[(size_t)(r0 + 8) * N + col] = L;
            }
            if (EPI == 5) {
                // stage transposed: tbuf[l_local][q_local], stride 132
                const int rm = wm + 16 * mi + qr;          // q_local
                const int cn = wn + 8 * ni + 2 * tc;       // l_local
                tbuf[(cn + 0) * 132 + rm]     = c0;
                tbuf[(cn + 1) * 132 + rm]     = c1;
                tbuf[(cn + 0) * 132 + rm + 8] = c2;
                tbuf[(cn + 1) * 132 + rm + 8] = c3;
            }
            if (EPI == 0 || EPI == 1 || EPI == 3) {
                float* C = Cb + (size_t)blockIdx.z * sC;
                *(float2*)(C + (size_t)r0 * N + col)       = make_float2(c0, c1);
                *(float2*)(C + (size_t)(r0 + 8) * N + col) = make_float2(c2, c3);
            }
        }
    }

    if (EPI == 5) {
        __syncthreads();
        // write out_am rows [b][l][q]: Cb layout [N_total=LL][M=QQ] per batch
        float* Ob = Cb + (size_t)blockIdx.z * sC;
#pragma unroll
        for (int j = 0; j < 16; j++) {
            int idx = tid + 256 * j;        // 0..4095 = 128 rows x 32 float4
            int l  = idx >> 5;
            int qc = idx & 31;
            float4 v = ((const float4*)(tbuf + l * 132))[qc];
            *(float4*)(Ob + (size_t)(n0 + l) * M + m0 + 4 * qc) = v;
        }
    }
}

// ---------------------------------------------------------------------------
// Transpose + split: in fp32 [z][R][C] -> oh/ol fp16 [z][C][R] (half2 stores).
// ---------------------------------------------------------------------------
__global__ __launch_bounds__(256) void split_tr_kernel(
    const float* __restrict__ in, __half* __restrict__ oh, __half* __restrict__ ol,
    int R, int C)
{
    const size_t zo = (size_t)blockIdx.z * R * C;
    const int r0 = blockIdx.y * 32, c0 = blockIdx.x * 32;
    const int tx = threadIdx.x, ty = threadIdx.y;
    const int tid = ty * 32 + tx;
    __shared__ float t[32][33];
#pragma unroll
    for (int i = 0; i < 4; i++)
        t[ty + 8 * i][tx] = in[zo + (size_t)(r0 + ty + 8 * i) * C + c0 + tx];
    __syncthreads();
    const int op = tid & 15;
#pragma unroll
    for (int j = 0; j < 2; j++) {
        int oc = (tid >> 4) + 16 * j;
        float v0 = t[2 * op][oc], v1 = t[2 * op + 1][oc];
        __half2 h = __floats2half2_rn(v0, v1);
        float2 hf = __half22float2(h);
        __half2 l = __floats2half2_rn(v0 - hf.x, v1 - hf.y);
        size_t o = zo + (size_t)(c0 + oc) * R + r0 + 2 * op;
        *(__half2*)(oh + o) = h;
        *(__half2*)(ol + o) = l;
    }
}

// Plain elementwise split: fp32[2*n2] -> h/l fp16.
__global__ __launch_bounds__(256) void split_plain_kernel(
    const float* __restrict__ in, __half* __restrict__ oh, __half* __restrict__ ol,
    size_t n2)
{
    size_t i = (size_t)blockIdx.x * 256 + threadIdx.x;
    if (i < n2) {
        float2 v = *(const float2*)(in + 2 * i);
        __half2 h = __floats2half2_rn(v.x, v.y);
        float2 hf = __half22float2(h);
        __half2 l = __floats2half2_rn(v.x - hf.x, v.y - hf.y);
        *(__half2*)(oh + 2 * i) = h;
        *(__half2*)(ol + 2 * i) = l;
    }
}

// ---------------------------------------------------------------------------
// Softmax over L=256, warp-per-row (8 rows/block); stores exp(p).
// ---------------------------------------------------------------------------
__global__ __launch_bounds__(256) void softmax_rows256(float* __restrict__ data)
{
    const int wid  = threadIdx.x >> 5;
    const int lane = threadIdx.x & 31;
    float* row = data + ((size_t)blockIdx.x * 8 + wid) * LL;

    float4 a = ((float4*)row)[lane];
    float4 b = ((float4*)row)[lane + 32];
    float m = fmaxf(fmaxf(fmaxf(a.x, a.y), fmaxf(a.z, a.w)),
                    fmaxf(fmaxf(b.x, b.y), fmaxf(b.z, b.w)));
#pragma unroll
    for (int o = 16; o; o >>= 1) m = fmaxf(m, __shfl_xor_sync(0xffffffffu, m, o));
    a.x = expf(a.x - m); a.y = expf(a.y - m); a.z = expf(a.z - m); a.w = expf(a.w - m);
    b.x = expf(b.x - m); b.y = expf(b.y - m); b.z = expf(b.z - m); b.w = expf(b.w - m);
    float s = a.x + a.y + a.z + a.w + b.x + b.y + b.z + b.w;
#pragma unroll
    for (int o = 16; o; o >>= 1) s += __shfl_xor_sync(0xffffffffu, s, o);
    const float inv = 1.0f / s;
    a.x = expf(a.x * inv); a.y = expf(a.y * inv); a.z = expf(a.z * inv); a.w = expf(a.w * inv);
    b.x = expf(b.x * inv); b.y = expf(b.y * inv); b.z = expf(b.z * inv); b.w = expf(b.w * inv);
    ((float4*)row)[lane]      = a;
    ((float4*)row)[lane + 32] = b;
}

// ---------------------------------------------------------------------------
// Second softmax (over Q): g_attn holds exp(p) -> plain sums -> reciprocal.
// ---------------------------------------------------------------------------
__global__ __launch_bounds__(256) void sumexp_partial_kernel()
{
    const int b = blockIdx.x;
    const int chunk = blockIdx.y;
    const int l = threadIdx.x;
    const size_t base = ((size_t)b * QQ + (size_t)chunk * 256) * LL + l;
    float s = 0.f;
#pragma unroll 8
    for (int q = 0; q < 256; q++) s += g_attn[base + (size_t)q * LL];
    g_partial[(b * 16 + chunk) * LL + l] = s;
}

__global__ __launch_bounds__(256) void sumexp_reduce_kernel()
{
    const int b = blockIdx.x;
    const int l = threadIdx.x;
    float s = 0.f;
#pragma unroll
    for (int c = 0; c < 16; c++) s += g_partial[(b * 16 + c) * LL + l];
    g_rsums[b * LL + l] = 1.0f / s;
}

// ---------------------------------------------------------------------------
// Launcher
// ---------------------------------------------------------------------------
extern "C" void kernel_launch(void* const* d_in, const int* in_sizes, int n_in,
                              void* d_out, int out_size)
{
    const float* x         = (const float*)d_in[0];
    const float* context   = (const float*)d_in[1];
    const float* w_context = (const float*)d_in[2];
    const float* w_img     = (const float*)d_in[3];
    const float* w_text    = (const float*)d_in[4];

    float* out_wc = (float*)d_out;
    float* out_am = out_wc + WC_ELEMS;

    float *p_source, *p_text, *p_attn;
    cudaGetSymbolAddress((void**)&p_source,  g_source);
    cudaGetSymbolAddress((void**)&p_text,    g_text);
    cudaGetSymbolAddress((void**)&p_attn,    g_attn);
    __half *xh, *xl, *ih, *il, *wh, *wl, *wch, *wcl, *wth, *wtl;
    __half *cth, *ctl, *sth, *stl, *tth, *ttl, *sh, *sl, *amh, *aml;
    cudaGetSymbolAddress((void**)&xh,  g_xT_h);   cudaGetSymbolAddress((void**)&xl,  g_xT_l);
    cudaGetSymbolAddress((void**)&ih,  g_imgT_h); cudaGetSymbolAddress((void**)&il,  g_imgT_l);
    cudaGetSymbolAddress((void**)&wh,  g_w_h);    cudaGetSymbolAddress((void**)&wl,  g_w_l);
    cudaGetSymbolAddress((void**)&wch, g_wc_h);   cudaGetSymbolAddress((void**)&wcl, g_wc_l);
    cudaGetSymbolAddress((void**)&wth, g_wt_h);   cudaGetSymbolAddress((void**)&wtl, g_wt_l);
    cudaGetSymbolAddress((void**)&cth, g_ctxT_h); cudaGetSymbolAddress((void**)&ctl, g_ctxT_l);
    cudaGetSymbolAddress((void**)&sth, g_srcT_h); cudaGetSymbolAddress((void**)&stl, g_srcT_l);
    cudaGetSymbolAddress((void**)&tth, g_txtT_h); cudaGetSymbolAddress((void**)&ttl, g_txtT_l);
    cudaGetSymbolAddress((void**)&sh,  g_src_h);  cudaGetSymbolAddress((void**)&sl,  g_src_l);
    cudaGetSymbolAddress((void**)&amh, g_am_h);   cudaGetSymbolAddress((void**)&aml, g_am_l);

    cudaFuncSetAttribute(hgemm_kernel<0, 3>, cudaFuncAttributeMaxDynamicSharedMemorySize, HG_SMEM);
    cudaFuncSetAttribute(hgemm_kernel<0, 2>, cudaFuncAttributeMaxDynamicSharedMemorySize, HG_SMEM);
    cudaFuncSetAttribute(hgemm_kernel<1, 3>, cudaFuncAttributeMaxDynamicSharedMemorySize, HG_SMEM);
    cudaFuncSetAttribute(hgemm_kernel<2, 3>, cudaFuncAttributeMaxDynamicSharedMemorySize, HG_SMEM);
    cudaFuncSetAttribute(hgemm_kernel<3, 3>, cudaFuncAttributeMaxDynamicSharedMemorySize, HG_SMEM);
    cudaFuncSetAttribute(hgemm_kernel<5, 3>, cudaFuncAttributeMaxDynamicSharedMemorySize, HG_SMEM);

    const long long sSL  = (long long)IDF_ * LL;
    const long long sQI  = (long long)QQ * IDF_;
    const long long sLI  = (long long)LL * IDF_;
    const long long sLC  = (long long)LL * CDF_;
    const long long sQL  = (long long)QQ * LL;
    const long long sIQ  = (long long)IDF_ * QQ;

    // 1) ctxT split: context [b][c][l] -> [b][l][c] h/l
    split_tr_kernel<<<dim3(LL / 32, CDF_ / 32, BB), dim3(32, 8)>>>(context, cth, ctl, CDF_, LL);
    // 2-3) weight splits
    split_plain_kernel<<<(IDF_ * CDF_ / 2 + 255) / 256, 256>>>(w_context, wch, wcl, IDF_ * CDF_ / 2);
    split_plain_kernel<<<(IDF_ * CDF_ / 2 + 255) / 256, 256>>>(w_text, wth, wtl, IDF_ * CDF_ / 2);
    // 4) source = wc @ ctxT^T -> fp32 [b][i][l] AND h/l  (PROFILED launch)
    hgemm_kernel<3, 3><<<dim3(2, 4, BB), 256, HG_SMEM>>>(
        wch, wcl, cth, ctl, p_source, sh, sl, IDF_, LL, CDF_, 0, sLC, sSL);
    // 5) xT split: x [b][i][q] -> [b][q][i] h/l
    split_tr_kernel<<<dim3(QQ / 32, IDF_ / 32, BB), dim3(32, 8)>>>(x, xh, xl, IDF_, QQ);
    // 6) text = tanh(wt @ ctxT^T) -> fp32 [b][i][l]
    hgemm_kernel<1, 3><<<dim3(2, 4, BB), 256, HG_SMEM>>>(
        wth, wtl, cth, ctl, p_text, nullptr, nullptr, IDF_, LL, CDF_, 0, sLC, sSL);
    // 7-8) srcT / txtT splits
    split_tr_kernel<<<dim3(LL / 32, IDF_ / 32, BB), dim3(32, 8)>>>(p_source, sth, stl, IDF_, LL);
    split_tr_kernel<<<dim3(LL / 32, IDF_ / 32, BB), dim3(32, 8)>>>(p_text, tth, ttl, IDF_, LL);
    // 9) w_img split
    split_plain_kernel<<<(IDF_ * CDF_ / 2 + 255) / 256, 256>>>(w_img, wh, wl, IDF_ * CDF_ / 2);
    // 10) attn = xT @ srcT^T -> fp32 [b][q][l]
    hgemm_kernel<0, 3><<<dim3(2, 32, BB), 256, HG_SMEM>>>(
        xh, xl, sth, stl, p_attn, nullptr, nullptr, QQ, LL, IDF_, sQI, sLI, sQL);
    // 11-13) softmax over L (stores exp(p)); second-softmax sums -> rsums
    softmax_rows256<<<BB * QQ / 8, 256>>>(p_attn);
    sumexp_partial_kernel<<<dim3(BB, 16), 256>>>();
    sumexp_reduce_kernel<<<BB, 256>>>();
    // 14) imgT = tanh(xT @ w^T) -> h/l [b][q][o]
    hgemm_kernel<2, 3><<<dim3(4, 32, BB), 256, HG_SMEM>>>(
        xh, xl, wh, wl, nullptr, ih, il, QQ, IDF_, IDF_, sQI, 0, sQI);
    // 15) combine GATED + fused transpose: v = tanh(imgT@txtT^T)*exp(p)*rsum
    //     -> am h/l [b][q][l] AND out_am fp32 [b][l][q] (direct)
    hgemm_kernel<5, 3><<<dim3(2, 32, BB), 256, HG_SMEM>>>(
        ih, il, tth, ttl, out_am, amh, aml, QQ, LL, IDF_, sQI, sLI, sQL);
    // 16) wc = source @ am^T -> fp32 [b][i][q]  (2-term split: ~2^-12 precision)
    hgemm_kernel<0, 2><<<dim3(32, 4, BB), 256, HG_SMEM>>>(
        sh, sl, amh, aml, out_wc, nullptr, nullptr, IDF_, QQ, LL, sSL, sQL, sIQ);
}

// round 16
// speedup vs baseline: 1.6426x; 1.1849x over previous
#include <cuda_runtime.h>
#include <cuda_fp16.h>
#include <math.h>
#include <stdint.h>

// Problem constants
#define BB   32
#define IDF_ 512
#define CDF_ 512
#define QQ   4096   // 64*64
#define LL   256

#define WC_ELEMS ((size_t)BB * IDF_ * QQ)

// ---------------------------------------------------------------------------
// Scratch (static device memory; no allocation at runtime)
// ---------------------------------------------------------------------------
__device__ float  g_source [(size_t)BB * IDF_ * LL];   // [b][i][l] fp32
__device__ float  g_text   [(size_t)BB * IDF_ * LL];   // [b][i][l] fp32
__device__ float  g_attn   [(size_t)BB * QQ  * LL];    // [b][q][l] fp32 (exp(p))
__device__ float  g_partial[BB * 16 * LL];
__device__ float  g_rsums  [BB * LL];
// fp16 hi/lo pre-split operands
__device__ __half g_xT_h  [(size_t)BB * QQ * IDF_];    // [b][q][i]
__device__ __half g_xT_l  [(size_t)BB * QQ * IDF_];
__device__ __half g_imgT_h[(size_t)BB * QQ * IDF_];    // [b][q][o]
__device__ __half g_imgT_l[(size_t)BB * QQ * IDF_];
__device__ __half g_w_h   [IDF_ * CDF_];               // w_img [o][i]
__device__ __half g_w_l   [IDF_ * CDF_];
__device__ __half g_wc_h  [IDF_ * CDF_];               // w_context [o][c]
__device__ __half g_wc_l  [IDF_ * CDF_];
__device__ __half g_wt_h  [IDF_ * CDF_];               // w_text [o][c]
__device__ __half g_wt_l  [IDF_ * CDF_];
__device__ __half g_ctxT_h[(size_t)BB * LL * CDF_];    // [b][l][c]
__device__ __half g_ctxT_l[(size_t)BB * LL * CDF_];
__device__ __half g_srcT_h[(size_t)BB * LL * IDF_];    // [b][l][i]
__device__ __half g_srcT_l[(size_t)BB * LL * IDF_];
__device__ __half g_txtT_h[(size_t)BB * LL * IDF_];    // [b][l][i]
__device__ __half g_txtT_l[(size_t)BB * LL * IDF_];
__device__ __half g_src_h [(size_t)BB * IDF_ * LL];    // [b][i][l]
__device__ __half g_src_l [(size_t)BB * IDF_ * LL];
__device__ __half g_am_h  [(size_t)BB * QQ * LL];      // [b][q][l]
__device__ __half g_am_l  [(size_t)BB * QQ * LL];

// ---------------------------------------------------------------------------
// Helpers
// ---------------------------------------------------------------------------
__device__ __forceinline__ void split2_f16(float v0, float v1,
                                           uint32_t& hi, uint32_t& lo) {
    __half2 h = __floats2half2_rn(v0, v1);
    float2 hf = __half22float2(h);
    __half2 l = __floats2half2_rn(v0 - hf.x, v1 - hf.y);
    hi = *(uint32_t*)&h;
    lo = *(uint32_t*)&l;
}
__device__ __forceinline__ void mma_f16(float* c, const uint32_t* a, const uint32_t* b) {
    asm volatile(
        "mma.sync.aligned.m16n8k16.row.col.f32.f16.f16.f32 "
        "{%0,%1,%2,%3}, {%4,%5,%6,%7}, {%8,%9}, {%0,%1,%2,%3};"
        : "+f"(c[0]), "+f"(c[1]), "+f"(c[2]), "+f"(c[3])
        : "r"(a[0]), "r"(a[1]), "r"(a[2]), "r"(a[3]), "r"(b[0]), "r"(b[1]));
}
__device__ __forceinline__ void cp_async16(uint32_t smem_dst, const void* gsrc) {
    asm volatile("cp.async.cg.shared.global [%0], [%1], 16;"
                 :: "r"(smem_dst), "l"(gsrc) : "memory");
}
#define CP_COMMIT() asm volatile("cp.async.commit_group;" ::: "memory")
#define CP_WAIT(n)  asm volatile("cp.async.wait_group %0;" :: "n"(n) : "memory")
#define LDSM4(r0, r1, r2, r3, addr) \
    asm volatile("ldmatrix.sync.aligned.m8n8.x4.shared.b16 {%0,%1,%2,%3}, [%4];" \
                 : "=r"(r0), "=r"(r1), "=r"(r2), "=r"(r3) : "r"(addr))

// ---------------------------------------------------------------------------
// Pure-fp16 hi/lo GEMM (Markidis split, fp32-equivalent at NTERMS=3):
//   C[M,N] = A * B^T,  A = Ah+Al [M][K] fp16 rm,  B = Bh+Bl [N][K] fp16 rm.
// EPI: 0 = fp32 C; 1 = tanh fp32 C; 2 = tanh + split to Ch/Cl fp16;
//      3 = fp32 C AND split to Ch/Cl fp16;
//      5 = gated combine: v = tanh(acc)*g_attn*g_rsums; split h/l to Ch/Cl
//          [q][l] AND write v TRANSPOSED to Cb as [l][q] via smem (N==LL).
// NTERMS: 3 = hh+hl+lh (~2^-22); 2 = hh+hl (~2^-12, for tanh/gate-protected C).
// Block tile 128x128, 8 warps (2x4), warp tile 64x32, 2 CTAs/SM.
// K-chunk 32, 3-stage cp.async ring. Smem per buffer: row r x 64B,
// 16B quarter qd at r*64+16*(qd^((r>>1)&3)).
// ---------------------------------------------------------------------------
#define STG_B  32768    // Ah 8K | Al 8K | Bh 8K | Bl 8K
#define HG_SMEM (3 * STG_B)

template <int EPI, int NTERMS>
__global__ __launch_bounds__(256, 2) void hgemm_kernel(
    const __half* __restrict__ Ahb, const __half* __restrict__ Alb,
    const __half* __restrict__ Bhb, const __half* __restrict__ Blb,
    float* __restrict__ Cb, __half* __restrict__ Chb, __half* __restrict__ Clb,
    int M, int N, int K,
    long long sA, long long sB, long long sC)
{
    extern __shared__ __align__(16) char dsm[];
    const uint32_t base = (uint32_t)__cvta_generic_to_shared(dsm);

    const __half* Ah = Ahb + (size_t)blockIdx.z * sA;
    const __half* Al = Alb + (size_t)blockIdx.z * sA;
    const __half* Bh = Bhb + (size_t)blockIdx.z * sB;
    const __half* Bl = Blb + (size_t)blockIdx.z * sB;

    const int tid  = threadIdx.x;
    const int lane = tid & 31;
    const int wid  = tid >> 5;
    const int m0   = blockIdx.y * 128;
    const int n0   = blockIdx.x * 128;
    const int wm   = (wid & 1) * 64;
    const int wn   = (wid >> 1) * 32;
    const int qr   = lane >> 2;
    const int tc   = lane & 3;
    const int rl   = lane & 15;
    const int khl  = lane >> 4;

    float acc[4][4][4];
#pragma unroll
    for (int i = 0; i < 4; i++)
#pragma unroll
        for (int j = 0; j < 4; j++)
#pragma unroll
            for (int v = 0; v < 4; v++) acc[i][j][v] = 0.f;

    const int st_r = tid >> 1;
    const int st_q = (tid & 1) * 2;
    const uint32_t st_d0 = st_r * 64 + 16 * ((st_q)     ^ ((st_r >> 1) & 3));
    const uint32_t st_d1 = st_r * 64 + 16 * ((st_q + 1) ^ ((st_r >> 1) & 3));

    auto issue_chunk = [&](int k0, int s) {
        const uint32_t sb = base + s * STG_B;
        const size_t ao = (size_t)(m0 + st_r) * K + k0 + st_q * 8;
        const size_t bo = (size_t)(n0 + st_r) * K + k0 + st_q * 8;
        cp_async16(sb + st_d0,          Ah + ao);
        cp_async16(sb + st_d1,          Ah + ao + 8);
        if (NTERMS == 3) {
            cp_async16(sb + 8192 + st_d0,   Al + ao);
            cp_async16(sb + 8192 + st_d1,   Al + ao + 8);
        }
        cp_async16(sb + 16384 + st_d0,  Bh + bo);
        cp_async16(sb + 16384 + st_d1,  Bh + bo + 8);
        cp_async16(sb + 24576 + st_d0,  Bl + bo);
        cp_async16(sb + 24576 + st_d1,  Bl + bo + 8);
        CP_COMMIT();
    };

    auto mma_chunk = [&](int c) {
        const uint32_t sb = base + (c % 3) * STG_B;
#pragma unroll
        for (int ks = 0; ks < 2; ks++) {
            const int qd = 2 * ks + khl;
            uint32_t bh[4][2], bl[4][2];
#pragma unroll
            for (int nip = 0; nip < 2; nip++) {
                int n = wn + 16 * nip + rl;
                uint32_t off = n * 64 + 16 * (qd ^ ((n >> 1) & 3));
                uint32_t t0, t1, t2, t3;
                LDSM4(t0, t1, t2, t3, sb + 16384 + off);
                bh[2 * nip][0] = t0; bh[2 * nip + 1][0] = t1;
                bh[2 * nip][1] = t2; bh[2 * nip + 1][1] = t3;
                LDSM4(t0, t1, t2, t3, sb + 24576 + off);
                bl[2 * nip][0] = t0; bl[2 * nip + 1][0] = t1;
                bl[2 * nip][1] = t2; bl[2 * nip + 1][1] = t3;
            }
#pragma unroll
            for (int mi = 0; mi < 4; mi++) {
                int r = wm + 16 * mi + rl;
                uint32_t off = r * 64 + 16 * (qd ^ ((r >> 1) & 3));
                uint32_t ah[4], al[4];
                LDSM4(ah[0], ah[1], ah[2], ah[3], sb + off);
                if (NTERMS == 3) LDSM4(al[0], al[1], al[2], al[3], sb + 8192 + off);
#pragma unroll
                for (int ni = 0; ni < 4; ni++) {
                    mma_f16(acc[mi][ni], ah, bh[ni]);
                    mma_f16(acc[mi][ni], ah, bl[ni]);
                    if (NTERMS == 3) mma_f16(acc[mi][ni], al, bh[ni]);
                }
            }
        }
    };

    const int nchunk = K >> 5;   // >= 8 for all calls
    issue_chunk(0, 0);
    issue_chunk(32, 1);

    for (int c = 0; c < nchunk; c++) {
        if (c + 1 < nchunk) CP_WAIT(1); else CP_WAIT(0);
        __syncthreads();
        if (c + 2 < nchunk) issue_chunk((c + 2) << 5, (c + 2) % 3);
        mma_chunk(c);
    }

    if (EPI == 5) __syncthreads();   // mainloop smem reads done before reuse
    float* tbuf = (float*)dsm;       // EPI==5: 128l x 128q tile, stride 132

    // ---- epilogue ----
#pragma unroll
    for (int mi = 0; mi < 4; mi++) {
#pragma unroll
        for (int ni = 0; ni < 4; ni++) {
            int r0  = m0 + wm + 16 * mi + qr;
            int col = n0 + wn + 8 * ni + 2 * tc;
            float c0 = acc[mi][ni][0], c1 = acc[mi][ni][1];
            float c2 = acc[mi][ni][2], c3 = acc[mi][ni][3];
            if (EPI == 1 || EPI == 2 || EPI == 5) {
                c0 = tanhf(c0); c1 = tanhf(c1); c2 = tanhf(c2); c3 = tanhf(c3);
            }
            if (EPI == 5) {
                // gate: v = tanh * exp(p) * rsum   (N == LL, layout == g_attn)
                const float* At = g_attn + (size_t)blockIdx.z * QQ * LL;
                const float* Rs = g_rsums + blockIdx.z * LL;
                float2 e0 = *(const float2*)&At[(size_t)r0 * N + col];
                float2 e1 = *(const float2*)&At[(size_t)(r0 + 8) * N + col];
                float2 rs = *(const float2*)&Rs[col];
                c0 *= e0.x * rs.x; c1 *= e0.y * rs.y;
                c2 *= e1.x * rs.x; c3 *= e1.y * rs.y;
            }
            if (EPI >= 2) {  // 2,3,5: split h/l
                __half* Ch = Chb + (size_t)blockIdx.z * sC;
                __half* Cl = Clb + (size_t)blockIdx.z * sC;
                uint32_t H, L;
                split2_f16(c0, c1, H, L);
                *(uint32_t*)&Ch[(size_t)r0 * N + col] = H;
                *(uint32_t*)&Cl[(size_t)r0 * N + col] = L;
                split2_f16(c2, c3, H, L);
                *(uint32_t*)&Ch[(size_t)(r0 + 8) * N + col] = H;
                *(uint32_t*)&Cl[(size_t)(r0 + 8) * N + col] = L;
            }
            if (EPI == 5) {
                // stage transposed: tbuf[l_local][q_local], stride 132
                const int rm = wm + 16 * mi + qr;          // q_local
                const int cn = wn + 8 * ni + 2 * tc;       // l_local
                tbuf[(cn + 0) * 132 + rm]     = c0;
                tbuf[(cn + 1) * 132 + rm]     = c1;
                tbuf[(cn + 0) * 132 + rm + 8] = c2;
                tbuf[(cn + 1) * 132 + rm + 8] = c3;
            }
            if (EPI == 0 || EPI == 1 || EPI == 3) {
                float* C = Cb + (size_t)blockIdx.z * sC;
                *(float2*)(C + (size_t)r0 * N + col)       = make_float2(c0, c1);
                *(float2*)(C + (size_t)(r0 + 8) * N + col) = make_float2(c2, c3);
            }
        }
    }

    if (EPI == 5) {
        __syncthreads();
        // write out_am rows [b][l][q]: Cb layout [N_total=LL][M=QQ] per batch
        float* Ob = Cb + (size_t)blockIdx.z * sC;
#pragma unroll
        for (int j = 0; j < 16; j++) {
            int idx = tid + 256 * j;        // 0..4095 = 128 rows x 32 float4
            int l  = idx >> 5;
            int qc = idx & 31;
            float4 v = ((const float4*)(tbuf + l * 132))[qc];
            *(float4*)(Ob + (size_t)(n0 + l) * M + m0 + 4 * qc) = v;
        }
    }
}

// ---------------------------------------------------------------------------
// Transpose + split: in fp32 [z][R][C] -> oh/ol fp16 [z][C][R] (half2 stores).
// ---------------------------------------------------------------------------
__global__ __launch_bounds__(256) void split_tr_kernel(
    const float* __restrict__ in, __half* __restrict__ oh, __half* __restrict__ ol,
    int R, int C)
{
    const size_t zo = (size_t)blockIdx.z * R * C;
    const int r0 = blockIdx.y * 32, c0 = blockIdx.x * 32;
    const int tx = threadIdx.x, ty = threadIdx.y;
    const int tid = ty * 32 + tx;
    __shared__ float t[32][33];
#pragma unroll
    for (int i = 0; i < 4; i++)
        t[ty + 8 * i][tx] = in[zo + (size_t)(r0 + ty + 8 * i) * C + c0 + tx];
    __syncthreads();
    const int op = tid & 15;
#pragma unroll
    for (int j = 0; j < 2; j++) {
        int oc = (tid >> 4) + 16 * j;
        float v0 = t[2 * op][oc], v1 = t[2 * op + 1][oc];
        __half2 h = __floats2half2_rn(v0, v1);
        float2 hf = __half22float2(h);
        __half2 l = __floats2half2_rn(v0 - hf.x, v1 - hf.y);
        size_t o = zo + (size_t)(c0 + oc) * R + r0 + 2 * op;
        *(__half2*)(oh + o) = h;
        *(__half2*)(ol + o) = l;
    }
}

// Plain elementwise split: fp32[2*n2] -> h/l fp16.
__global__ __launch_bounds__(256) void split_plain_kernel(
    const float* __restrict__ in, __half* __restrict__ oh, __half* __restrict__ ol,
    size_t n2)
{
    size_t i = (size_t)blockIdx.x * 256 + threadIdx.x;
    if (i < n2) {
        float2 v = *(const float2*)(in + 2 * i);
        __half2 h = __floats2half2_rn(v.x, v.y);
        float2 hf = __half22float2(h);
        __half2 l = __floats2half2_rn(v.x - hf.x, v.y - hf.y);
        *(__half2*)(oh + 2 * i) = h;
        *(__half2*)(ol + 2 * i) = l;
    }
}

// ---------------------------------------------------------------------------
// Softmax over L=256, warp-per-row (8 rows/block); stores exp(p).
// ---------------------------------------------------------------------------
__global__ __launch_bounds__(256) void softmax_rows256(float* __restrict__ data)
{
    const int wid  = threadIdx.x >> 5;
    const int lane = threadIdx.x & 31;
    float* row = data + ((size_t)blockIdx.x * 8 + wid) * LL;

    float4 a = ((float4*)row)[lane];
    float4 b = ((float4*)row)[lane + 32];
    float m = fmaxf(fmaxf(fmaxf(a.x, a.y), fmaxf(a.z, a.w)),
                    fmaxf(fmaxf(b.x, b.y), fmaxf(b.z, b.w)));
#pragma unroll
    for (int o = 16; o; o >>= 1) m = fmaxf(m, __shfl_xor_sync(0xffffffffu, m, o));
    a.x = expf(a.x - m); a.y = expf(a.y - m); a.z = expf(a.z - m); a.w = expf(a.w - m);
    b.x = expf(b.x - m); b.y = expf(b.y - m); b.z = expf(b.z - m); b.w = expf(b.w - m);
    float s = a.x + a.y + a.z + a.w + b.x + b.y + b.z + b.w;
#pragma unroll
    for (int o = 16; o; o >>= 1) s += __shfl_xor_sync(0xffffffffu, s, o);
    const float inv = 1.0f / s;
    a.x = expf(a.x * inv); a.y = expf(a.y * inv); a.z = expf(a.z * inv); a.w = expf(a.w * inv);
    b.x = expf(b.x * inv); b.y = expf(b.y * inv); b.z = expf(b.z * inv); b.w = expf(b.w * inv);
    ((float4*)row)[lane]      = a;
    ((float4*)row)[lane + 32] = b;
}

// ---------------------------------------------------------------------------
// Second softmax (over Q): g_attn holds exp(p) -> plain sums -> reciprocal.
// ---------------------------------------------------------------------------
__global__ __launch_bounds__(256) void sumexp_partial_kernel()
{
    const int b = blockIdx.x;
    const int chunk = blockIdx.y;
    const int l = threadIdx.x;
    const size_t base = ((size_t)b * QQ + (size_t)chunk * 256) * LL + l;
    float s = 0.f;
#pragma unroll 8
    for (int q = 0; q < 256; q++) s += g_attn[base + (size_t)q * LL];
    g_partial[(b * 16 + chunk) * LL + l] = s;
}

__global__ __launch_bounds__(256) void sumexp_reduce_kernel()
{
    const int b = blockIdx.x;
    const int l = threadIdx.x;
    float s = 0.f;
#pragma unroll
    for (int c = 0; c < 16; c++) s += g_partial[(b * 16 + c) * LL + l];
    g_rsums[b * LL + l] = 1.0f / s;
}

// ---------------------------------------------------------------------------
// Launcher
// ---------------------------------------------------------------------------
extern "C" void kernel_launch(void* const* d_in, const int* in_sizes, int n_in,
                              void* d_out, int out_size)
{
    const float* x         = (const float*)d_in[0];
    const float* context   = (const float*)d_in[1];
    const float* w_context = (const float*)d_in[2];
    const float* w_img     = (const float*)d_in[3];
    const float* w_text    = (const float*)d_in[4];

    float* out_wc = (float*)d_out;
    float* out_am = out_wc + WC_ELEMS;

    float *p_source, *p_text, *p_attn;
    cudaGetSymbolAddress((void**)&p_source,  g_source);
    cudaGetSymbolAddress((void**)&p_text,    g_text);
    cudaGetSymbolAddress((void**)&p_attn,    g_attn);
    __half *xh, *xl, *ih, *il, *wh, *wl, *wch, *wcl, *wth, *wtl;
    __half *cth, *ctl, *sth, *stl, *tth, *ttl, *sh, *sl, *amh, *aml;
    cudaGetSymbolAddress((void**)&xh,  g_xT_h);   cudaGetSymbolAddress((void**)&xl,  g_xT_l);
    cudaGetSymbolAddress((void**)&ih,  g_imgT_h); cudaGetSymbolAddress((void**)&il,  g_imgT_l);
    cudaGetSymbolAddress((void**)&wh,  g_w_h);    cudaGetSymbolAddress((void**)&wl,  g_w_l);
    cudaGetSymbolAddress((void**)&wch, g_wc_h);   cudaGetSymbolAddress((void**)&wcl, g_wc_l);
    cudaGetSymbolAddress((void**)&wth, g_wt_h);   cudaGetSymbolAddress((void**)&wtl, g_wt_l);
    cudaGetSymbolAddress((void**)&cth, g_ctxT_h); cudaGetSymbolAddress((void**)&ctl, g_ctxT_l);
    cudaGetSymbolAddress((void**)&sth, g_srcT_h); cudaGetSymbolAddress((void**)&stl, g_srcT_l);
    cudaGetSymbolAddress((void**)&tth, g_txtT_h); cudaGetSymbolAddress((void**)&ttl, g_txtT_l);
    cudaGetSymbolAddress((void**)&sh,  g_src_h);  cudaGetSymbolAddress((void**)&sl,  g_src_l);
    cudaGetSymbolAddress((void**)&amh, g_am_h);   cudaGetSymbolAddress((void**)&aml, g_am_l);

    cudaFuncSetAttribute(hgemm_kernel<0, 3>, cudaFuncAttributeMaxDynamicSharedMemorySize, HG_SMEM);
    cudaFuncSetAttribute(hgemm_kernel<0, 2>, cudaFuncAttributeMaxDynamicSharedMemorySize, HG_SMEM);
    cudaFuncSetAttribute(hgemm_kernel<1, 3>, cudaFuncAttributeMaxDynamicSharedMemorySize, HG_SMEM);
    cudaFuncSetAttribute(hgemm_kernel<2, 2>, cudaFuncAttributeMaxDynamicSharedMemorySize, HG_SMEM);
    cudaFuncSetAttribute(hgemm_kernel<3, 3>, cudaFuncAttributeMaxDynamicSharedMemorySize, HG_SMEM);
    cudaFuncSetAttribute(hgemm_kernel<5, 2>, cudaFuncAttributeMaxDynamicSharedMemorySize, HG_SMEM);

    const long long sSL  = (long long)IDF_ * LL;
    const long long sQI  = (long long)QQ * IDF_;
    const long long sLI  = (long long)LL * IDF_;
    const long long sLC  = (long long)LL * CDF_;
    const long long sQL  = (long long)QQ * LL;
    const long long sIQ  = (long long)IDF_ * QQ;

    // 1) ctxT split: context [b][c][l] -> [b][l][c] h/l
    split_tr_kernel<<<dim3(LL / 32, CDF_ / 32, BB), dim3(32, 8)>>>(context, cth, ctl, CDF_, LL);
    // 2-3) weight splits
    split_plain_kernel<<<(IDF_ * CDF_ / 2 + 255) / 256, 256>>>(w_context, wch, wcl, IDF_ * CDF_ / 2);
    split_plain_kernel<<<(IDF_ * CDF_ / 2 + 255) / 256, 256>>>(w_text, wth, wtl, IDF_ * CDF_ / 2);
    // 4) source = wc @ ctxT^T -> fp32 [b][i][l] AND h/l  (3-term: feeds logits)
    hgemm_kernel<3, 3><<<dim3(2, 4, BB), 256, HG_SMEM>>>(
        wch, wcl, cth, ctl, p_source, sh, sl, IDF_, LL, CDF_, 0, sLC, sSL);
    // 5) xT split: x [b][i][q] -> [b][q][i] h/l
    split_tr_kernel<<<dim3(QQ / 32, IDF_ / 32, BB), dim3(32, 8)>>>(x, xh, xl, IDF_, QQ);
    // 6) text = tanh(wt @ ctxT^T) -> fp32 [b][i][l]
    hgemm_kernel<1, 3><<<dim3(2, 4, BB), 256, HG_SMEM>>>(
        wth, wtl, cth, ctl, p_text, nullptr, nullptr, IDF_, LL, CDF_, 0, sLC, sSL);
    // 7-8) srcT / txtT splits
    split_tr_kernel<<<dim3(LL / 32, IDF_ / 32, BB), dim3(32, 8)>>>(p_source, sth, stl, IDF_, LL);
    split_tr_kernel<<<dim3(LL / 32, IDF_ / 32, BB), dim3(32, 8)>>>(p_text, tth, ttl, IDF_, LL);
    // 9) w_img split
    split_plain_kernel<<<(IDF_ * CDF_ / 2 + 255) / 256, 256>>>(w_img, wh, wl, IDF_ * CDF_ / 2);
    // 10) attn = xT @ srcT^T -> fp32 [b][q][l]  (3-term: softmax-critical)
    hgemm_kernel<0, 3><<<dim3(2, 32, BB), 256, HG_SMEM>>>(
        xh, xl, sth, stl, p_attn, nullptr, nullptr, QQ, LL, IDF_, sQI, sLI, sQL);
    // 11-13) softmax over L (stores exp(p)); second-softmax sums -> rsums
    softmax_rows256<<<BB * QQ / 8, 256>>>(p_attn);
    sumexp_partial_kernel<<<dim3(BB, 16), 256>>>();
    sumexp_reduce_kernel<<<BB, 256>>>();
    // 14) imgT = tanh(xT @ w^T) -> h/l [b][q][o]  (2-term: tanh-protected)
    hgemm_kernel<2, 2><<<dim3(4, 32, BB), 256, HG_SMEM>>>(
        xh, xl, wh, wl, nullptr, ih, il, QQ, IDF_, IDF_, sQI, 0, sQI);
    // 15) combine GATED + fused transpose (2-term): v = tanh(.)*exp(p)*rsum
    //     -> am h/l [b][q][l] AND out_am fp32 [b][l][q]
    hgemm_kernel<5, 2><<<dim3(2, 32, BB), 256, HG_SMEM>>>(
        ih, il, tth, ttl, out_am, amh, aml, QQ, LL, IDF_, sQI, sLI, sQL);
    // 16) wc = source @ am^T -> fp32 [b][i][q]  (2-term)
    hgemm_kernel<0, 2><<<dim3(32, 4, BB), 256, HG_SMEM>>>(
        sh, sl, amh, aml, out_wc, nullptr, nullptr, IDF_, QQ, LL, sSL, sQL, sIQ);
}

// round 17
// speedup vs baseline: 1.8560x; 1.1299x over previous
#include <cuda_runtime.h>
#include <cuda_fp16.h>
#include <math.h>
#include <stdint.h>

// Problem constants
#define BB   32
#define IDF_ 512
#define CDF_ 512
#define QQ   4096   // 64*64
#define LL   256

#define WC_ELEMS ((size_t)BB * IDF_ * QQ)

// ---------------------------------------------------------------------------
// Scratch (static device memory; no allocation at runtime)
// ---------------------------------------------------------------------------
__device__ float  g_attn   [(size_t)BB * QQ  * LL];    // [b][q][l] fp32 (exp(p))
__device__ float  g_partial[BB * 16 * LL];
__device__ float  g_rsums  [BB * LL];
// fp16 hi/lo pre-split operands
__device__ __half g_xT_h  [(size_t)BB * QQ * IDF_];    // [b][q][i]
__device__ __half g_xT_l  [(size_t)BB * QQ * IDF_];
__device__ __half g_imgT_h[(size_t)BB * QQ * IDF_];    // [b][q][o]
__device__ __half g_imgT_l[(size_t)BB * QQ * IDF_];
__device__ __half g_w_h   [IDF_ * CDF_];               // w_img [o][i]
__device__ __half g_w_l   [IDF_ * CDF_];
__device__ __half g_wc_h  [IDF_ * CDF_];               // w_context [o][c]
__device__ __half g_wc_l  [IDF_ * CDF_];
__device__ __half g_wt_h  [IDF_ * CDF_];               // w_text [o][c]
__device__ __half g_wt_l  [IDF_ * CDF_];
__device__ __half g_ctxT_h[(size_t)BB * LL * CDF_];    // [b][l][c]
__device__ __half g_ctxT_l[(size_t)BB * LL * CDF_];
__device__ __half g_srcT_h[(size_t)BB * LL * IDF_];    // [b][l][i]
__device__ __half g_srcT_l[(size_t)BB * LL * IDF_];
__device__ __half g_txtT_h[(size_t)BB * LL * IDF_];    // [b][l][i]
__device__ __half g_txtT_l[(size_t)BB * LL * IDF_];
__device__ __half g_src_h [(size_t)BB * IDF_ * LL];    // [b][i][l]
__device__ __half g_src_l [(size_t)BB * IDF_ * LL];
__device__ __half g_am_h  [(size_t)BB * QQ * LL];      // [b][q][l]
__device__ __half g_am_l  [(size_t)BB * QQ * LL];

// ---------------------------------------------------------------------------
// Helpers
// ---------------------------------------------------------------------------
__device__ __forceinline__ void split2_f16(float v0, float v1,
                                           uint32_t& hi, uint32_t& lo) {
    __half2 h = __floats2half2_rn(v0, v1);
    float2 hf = __half22float2(h);
    __half2 l = __floats2half2_rn(v0 - hf.x, v1 - hf.y);
    hi = *(uint32_t*)&h;
    lo = *(uint32_t*)&l;
}
__device__ __forceinline__ void mma_f16(float* c, const uint32_t* a, const uint32_t* b) {
    asm volatile(
        "mma.sync.aligned.m16n8k16.row.col.f32.f16.f16.f32 "
        "{%0,%1,%2,%3}, {%4,%5,%6,%7}, {%8,%9}, {%0,%1,%2,%3};"
        : "+f"(c[0]), "+f"(c[1]), "+f"(c[2]), "+f"(c[3])
        : "r"(a[0]), "r"(a[1]), "r"(a[2]), "r"(a[3]), "r"(b[0]), "r"(b[1]));
}
__device__ __forceinline__ void cp_async16(uint32_t smem_dst, const void* gsrc) {
    asm volatile("cp.async.cg.shared.global [%0], [%1], 16;"
                 :: "r"(smem_dst), "l"(gsrc) : "memory");
}
#define CP_COMMIT() asm volatile("cp.async.commit_group;" ::: "memory")
#define CP_WAIT(n)  asm volatile("cp.async.wait_group %0;" :: "n"(n) : "memory")
#define LDSM4(r0, r1, r2, r3, addr) \
    asm volatile("ldmatrix.sync.aligned.m8n8.x4.shared.b16 {%0,%1,%2,%3}, [%4];" \
                 : "=r"(r0), "=r"(r1), "=r"(r2), "=r"(r3) : "r"(addr))

// ---------------------------------------------------------------------------
// Pure-fp16 hi/lo GEMM (Markidis split):
//   C[M,N] = A * B^T,  A = Ah+Al [M][K] fp16 rm,  B = Bh+Bl [N][K] fp16 rm.
// NTERMS: 3 = hh+hl+lh (~2^-22); 2 = hh+hl (~2^-12); 1 = hh (~2^-11).
// EPI: 0 = fp32 C; 2 = tanh + split h/l to Ch/Cl;
//      5 = gated combine: v = tanh(acc)*g_attn*g_rsums; split h/l [q][l]
//          AND v transposed to Cb fp32 [l][q] via smem (N==LL);
//      6 = split h/l [m][n] to Ch/Cl AND transposed h/l [n][m] to Th/Tl;
//      7 = tanh, transposed h/l [n][m] to Th/Tl only.
// Block tile 128x128, 8 warps (2x4), warp tile 64x32, 2 CTAs/SM.
// K-chunk 32, 3-stage cp.async ring. Smem per buffer: row r x 64B,
// 16B quarter qd at r*64+16*(qd^((r>>1)&3)).
// ---------------------------------------------------------------------------
#define STG_B  32768    // Ah 8K | Al 8K | Bh 8K | Bl 8K
#define HG_SMEM (3 * STG_B)

template <int EPI, int NTERMS>
__global__ __launch_bounds__(256, 2) void hgemm_kernel(
    const __half* __restrict__ Ahb, const __half* __restrict__ Alb,
    const __half* __restrict__ Bhb, const __half* __restrict__ Blb,
    float* __restrict__ Cb, __half* __restrict__ Chb, __half* __restrict__ Clb,
    __half* __restrict__ Thb, __half* __restrict__ Tlb,
    int M, int N, int K,
    long long sA, long long sB, long long sC, long long sT)
{
    extern __shared__ __align__(16) char dsm[];
    const uint32_t base = (uint32_t)__cvta_generic_to_shared(dsm);

    const __half* Ah = Ahb + (size_t)blockIdx.z * sA;
    const __half* Al = Alb + (size_t)blockIdx.z * sA;
    const __half* Bh = Bhb + (size_t)blockIdx.z * sB;
    const __half* Bl = Blb + (size_t)blockIdx.z * sB;

    const int tid  = threadIdx.x;
    const int lane = tid & 31;
    const int wid  = tid >> 5;
    const int m0   = blockIdx.y * 128;
    const int n0   = blockIdx.x * 128;
    const int wm   = (wid & 1) * 64;
    const int wn   = (wid >> 1) * 32;
    const int qr   = lane >> 2;
    const int tc   = lane & 3;
    const int rl   = lane & 15;
    const int khl  = lane >> 4;

    float acc[4][4][4];
#pragma unroll
    for (int i = 0; i < 4; i++)
#pragma unroll
        for (int j = 0; j < 4; j++)
#pragma unroll
            for (int v = 0; v < 4; v++) acc[i][j][v] = 0.f;

    const int st_r = tid >> 1;
    const int st_q = (tid & 1) * 2;
    const uint32_t st_d0 = st_r * 64 + 16 * ((st_q)     ^ ((st_r >> 1) & 3));
    const uint32_t st_d1 = st_r * 64 + 16 * ((st_q + 1) ^ ((st_r >> 1) & 3));

    auto issue_chunk = [&](int k0, int s) {
        const uint32_t sb = base + s * STG_B;
        const size_t ao = (size_t)(m0 + st_r) * K + k0 + st_q * 8;
        const size_t bo = (size_t)(n0 + st_r) * K + k0 + st_q * 8;
        cp_async16(sb + st_d0,          Ah + ao);
        cp_async16(sb + st_d1,          Ah + ao + 8);
        if (NTERMS == 3) {
            cp_async16(sb + 8192 + st_d0,   Al + ao);
            cp_async16(sb + 8192 + st_d1,   Al + ao + 8);
        }
        cp_async16(sb + 16384 + st_d0,  Bh + bo);
        cp_async16(sb + 16384 + st_d1,  Bh + bo + 8);
        if (NTERMS >= 2) {
            cp_async16(sb + 24576 + st_d0,  Bl + bo);
            cp_async16(sb + 24576 + st_d1,  Bl + bo + 8);
        }
        CP_COMMIT();
    };

    auto mma_chunk = [&](int c) {
        const uint32_t sb = base + (c % 3) * STG_B;
#pragma unroll
        for (int ks = 0; ks < 2; ks++) {
            const int qd = 2 * ks + khl;
            uint32_t bh[4][2], bl[4][2];
#pragma unroll
            for (int nip = 0; nip < 2; nip++) {
                int n = wn + 16 * nip + rl;
                uint32_t off = n * 64 + 16 * (qd ^ ((n >> 1) & 3));
                uint32_t t0, t1, t2, t3;
                LDSM4(t0, t1, t2, t3, sb + 16384 + off);
                bh[2 * nip][0] = t0; bh[2 * nip + 1][0] = t1;
                bh[2 * nip][1] = t2; bh[2 * nip + 1][1] = t3;
                if (NTERMS >= 2) {
                    LDSM4(t0, t1, t2, t3, sb + 24576 + off);
                    bl[2 * nip][0] = t0; bl[2 * nip + 1][0] = t1;
                    bl[2 * nip][1] = t2; bl[2 * nip + 1][1] = t3;
                }
            }
#pragma unroll
            for (int mi = 0; mi < 4; mi++) {
                int r = wm + 16 * mi + rl;
                uint32_t off = r * 64 + 16 * (qd ^ ((r >> 1) & 3));
                uint32_t ah[4], al[4];
                LDSM4(ah[0], ah[1], ah[2], ah[3], sb + off);
                if (NTERMS == 3) LDSM4(al[0], al[1], al[2], al[3], sb + 8192 + off);
#pragma unroll
                for (int ni = 0; ni < 4; ni++) {
                    mma_f16(acc[mi][ni], ah, bh[ni]);
                    if (NTERMS >= 2) mma_f16(acc[mi][ni], ah, bl[ni]);
                    if (NTERMS == 3) mma_f16(acc[mi][ni], al, bh[ni]);
                }
            }
        }
    };

    const int nchunk = K >> 5;   // >= 8 for all calls
    issue_chunk(0, 0);
    issue_chunk(32, 1);

    for (int c = 0; c < nchunk; c++) {
        if (c + 1 < nchunk) CP_WAIT(1); else CP_WAIT(0);
        __syncthreads();
        if (c + 2 < nchunk) issue_chunk((c + 2) << 5, (c + 2) % 3);
        mma_chunk(c);
    }

    constexpr bool TRANS = (EPI == 5 || EPI == 6 || EPI == 7);
    if (TRANS) __syncthreads();      // mainloop smem reads done before reuse
    float* tbuf = (float*)dsm;       // 128n x 128m tile, stride 132

    // ---- epilogue ----
#pragma unroll
    for (int mi = 0; mi < 4; mi++) {
#pragma unroll
        for (int ni = 0; ni < 4; ni++) {
            int r0  = m0 + wm + 16 * mi + qr;
            int col = n0 + wn + 8 * ni + 2 * tc;
            float c0 = acc[mi][ni][0], c1 = acc[mi][ni][1];
            float c2 = acc[mi][ni][2], c3 = acc[mi][ni][3];
            if (EPI == 2 || EPI == 5 || EPI == 7) {
                c0 = tanhf(c0); c1 = tanhf(c1); c2 = tanhf(c2); c3 = tanhf(c3);
            }
            if (EPI == 5) {
                // gate: v = tanh * exp(p) * rsum   (N == LL, layout == g_attn)
                const float* At = g_attn + (size_t)blockIdx.z * QQ * LL;
                const float* Rs = g_rsums + blockIdx.z * LL;
                float2 e0 = *(const float2*)&At[(size_t)r0 * N + col];
                float2 e1 = *(const float2*)&At[(size_t)(r0 + 8) * N + col];
                float2 rs = *(const float2*)&Rs[col];
                c0 *= e0.x * rs.x; c1 *= e0.y * rs.y;
                c2 *= e1.x * rs.x; c3 *= e1.y * rs.y;
            }
            if (EPI == 2 || EPI == 5 || EPI == 6) {   // split h/l [m][n]
                __half* Ch = Chb + (size_t)blockIdx.z * sC;
                __half* Cl = Clb + (size_t)blockIdx.z * sC;
                uint32_t H, L;
                split2_f16(c0, c1, H, L);
                *(uint32_t*)&Ch[(size_t)r0 * N + col] = H;
                *(uint32_t*)&Cl[(size_t)r0 * N + col] = L;
                split2_f16(c2, c3, H, L);
                *(uint32_t*)&Ch[(size_t)(r0 + 8) * N + col] = H;
                *(uint32_t*)&Cl[(size_t)(r0 + 8) * N + col] = L;
            }
            if (TRANS) {
                // stage transposed: tbuf[n_local][m_local], stride 132
                const int rm = wm + 16 * mi + qr;
                const int cn = wn + 8 * ni + 2 * tc;
                tbuf[(cn + 0) * 132 + rm]     = c0;
                tbuf[(cn + 1) * 132 + rm]     = c1;
                tbuf[(cn + 0) * 132 + rm + 8] = c2;
                tbuf[(cn + 1) * 132 + rm + 8] = c3;
            }
            if (EPI == 0) {
                float* C = Cb + (size_t)blockIdx.z * sC;
                *(float2*)(C + (size_t)r0 * N + col)       = make_float2(c0, c1);
                *(float2*)(C + (size_t)(r0 + 8) * N + col) = make_float2(c2, c3);
            }
        }
    }

    if (TRANS) {
        __syncthreads();
        if (EPI == 5) {
            // fp32 transposed rows -> Cb [n][m]  (out_am [l][q])
            float* Ob = Cb + (size_t)blockIdx.z * sC;
#pragma unroll
            for (int j = 0; j < 16; j++) {
                int idx = tid + 256 * j;
                int n = idx >> 5, qc = idx & 31;
                float4 v = ((const float4*)(tbuf + n * 132))[qc];
                *(float4*)(Ob + (size_t)(n0 + n) * M + m0 + 4 * qc) = v;
            }
        } else {
            // h/l transposed rows -> Thb/Tlb [n][m]
            __half* Th = Thb + (size_t)blockIdx.z * sT;
            __half* Tl = Tlb + (size_t)blockIdx.z * sT;
#pragma unroll
            for (int j = 0; j < 16; j++) {
                int idx = tid + 256 * j;
                int n = idx >> 5, qc = idx & 31;
                float4 v = ((const float4*)(tbuf + n * 132))[qc];
                uint32_t h0, l0, h1, l1;
                split2_f16(v.x, v.y, h0, l0);
                split2_f16(v.z, v.w, h1, l1);
                size_t o = (size_t)(n0 + n) * M + m0 + 4 * qc;
                *(uint2*)&Th[o] = make_uint2(h0, h1);
                *(uint2*)&Tl[o] = make_uint2(l0, l1);
            }
        }
    }
}

// ---------------------------------------------------------------------------
// Transpose + split: in fp32 [z][R][C] -> oh/ol fp16 [z][C][R] (half2 stores).
// ---------------------------------------------------------------------------
__global__ __launch_bounds__(256) void split_tr_kernel(
    const float* __restrict__ in, __half* __restrict__ oh, __half* __restrict__ ol,
    int R, int C)
{
    const size_t zo = (size_t)blockIdx.z * R * C;
    const int r0 = blockIdx.y * 32, c0 = blockIdx.x * 32;
    const int tx = threadIdx.x, ty = threadIdx.y;
    const int tid = ty * 32 + tx;
    __shared__ float t[32][33];
#pragma unroll
    for (int i = 0; i < 4; i++)
        t[ty + 8 * i][tx] = in[zo + (size_t)(r0 + ty + 8 * i) * C + c0 + tx];
    __syncthreads();
    const int op = tid & 15;
#pragma unroll
    for (int j = 0; j < 2; j++) {
        int oc = (tid >> 4) + 16 * j;
        float v0 = t[2 * op][oc], v1 = t[2 * op + 1][oc];
        __half2 h = __floats2half2_rn(v0, v1);
        float2 hf = __half22float2(h);
        __half2 l = __floats2half2_rn(v0 - hf.x, v1 - hf.y);
        size_t o = zo + (size_t)(c0 + oc) * R + r0 + 2 * op;
        *(__half2*)(oh + o) = h;
        *(__half2*)(ol + o) = l;
    }
}

// Merged weight splits: 3 independent fp32 arrays -> h/l fp16 (blockIdx.y picks).
__global__ __launch_bounds__(256) void split_weights3_kernel(
    const float* __restrict__ i0, __half* __restrict__ o0h, __half* __restrict__ o0l,
    const float* __restrict__ i1, __half* __restrict__ o1h, __half* __restrict__ o1l,
    const float* __restrict__ i2, __half* __restrict__ o2h, __half* __restrict__ o2l)
{
    const float* in = (blockIdx.y == 0) ? i0 : (blockIdx.y == 1) ? i1 : i2;
    __half* oh = (blockIdx.y == 0) ? o0h : (blockIdx.y == 1) ? o1h : o2h;
    __half* ol = (blockIdx.y == 0) ? o0l : (blockIdx.y == 1) ? o1l : o2l;
    size_t i = (size_t)blockIdx.x * 256 + threadIdx.x;   // half2 index
    float2 v = *(const float2*)(in + 2 * i);
    __half2 h = __floats2half2_rn(v.x, v.y);
    float2 hf = __half22float2(h);
    __half2 l = __floats2half2_rn(v.x - hf.x, v.y - hf.y);
    *(__half2*)(oh + 2 * i) = h;
    *(__half2*)(ol + 2 * i) = l;
}

// ---------------------------------------------------------------------------
// Softmax over L=256, warp-per-row (8 rows/block); stores exp(p).
// ---------------------------------------------------------------------------
__global__ __launch_bounds__(256) void softmax_rows256(float* __restrict__ data)
{
    const int wid  = threadIdx.x >> 5;
    const int lane = threadIdx.x & 31;
    float* row = data + ((size_t)blockIdx.x * 8 + wid) * LL;

    float4 a = ((float4*)row)[lane];
    float4 b = ((float4*)row)[lane + 32];
    float m = fmaxf(fmaxf(fmaxf(a.x, a.y), fmaxf(a.z, a.w)),
                    fmaxf(fmaxf(b.x, b.y), fmaxf(b.z, b.w)));
#pragma unroll
    for (int o = 16; o; o >>= 1) m = fmaxf(m, __shfl_xor_sync(0xffffffffu, m, o));
    a.x = expf(a.x - m); a.y = expf(a.y - m); a.z = expf(a.z - m); a.w = expf(a.w - m);
    b.x = expf(b.x - m); b.y = expf(b.y - m); b.z = expf(b.z - m); b.w = expf(b.w - m);
    float s = a.x + a.y + a.z + a.w + b.x + b.y + b.z + b.w;
#pragma unroll
    for (int o = 16; o; o >>= 1) s += __shfl_xor_sync(0xffffffffu, s, o);
    const float inv = 1.0f / s;
    a.x = expf(a.x * inv); a.y = expf(a.y * inv); a.z = expf(a.z * inv); a.w = expf(a.w * inv);
    b.x = expf(b.x * inv); b.y = expf(b.y * inv); b.z = expf(b.z * inv); b.w = expf(b.w * inv);
    ((float4*)row)[lane]      = a;
    ((float4*)row)[lane + 32] = b;
}

// ---------------------------------------------------------------------------
// Second softmax (over Q): g_attn holds exp(p) -> plain sums -> reciprocal.
// ---------------------------------------------------------------------------
__global__ __launch_bounds__(256) void sumexp_partial_kernel()
{
    const int b = blockIdx.x;
    const int chunk = blockIdx.y;
    const int l = threadIdx.x;
    const size_t base = ((size_t)b * QQ + (size_t)chunk * 256) * LL + l;
    float s = 0.f;
#pragma unroll 8
    for (int q = 0; q < 256; q++) s += g_attn[base + (size_t)q * LL];
    g_partial[(b * 16 + chunk) * LL + l] = s;
}

__global__ __launch_bounds__(256) void sumexp_reduce_kernel()
{
    const int b = blockIdx.x;
    const int l = threadIdx.x;
    float s = 0.f;
#pragma unroll
    for (int c = 0; c < 16; c++) s += g_partial[(b * 16 + c) * LL + l];
    g_rsums[b * LL + l] = 1.0f / s;
}

// ---------------------------------------------------------------------------
// Launcher
// ---------------------------------------------------------------------------
extern "C" void kernel_launch(void* const* d_in, const int* in_sizes, int n_in,
                              void* d_out, int out_size)
{
    const float* x         = (const float*)d_in[0];
    const float* context   = (const float*)d_in[1];
    const float* w_context = (const float*)d_in[2];
    const float* w_img     = (const float*)d_in[3];
    const float* w_text    = (const float*)d_in[4];

    float* out_wc = (float*)d_out;
    float* out_am = out_wc + WC_ELEMS;

    float* p_attn;
    cudaGetSymbolAddress((void**)&p_attn, g_attn);
    __half *xh, *xl, *ih, *il, *wh, *wl, *wch, *wcl, *wth, *wtl;
    __half *cth, *ctl, *sth, *stl, *tth, *ttl, *sh, *sl, *amh, *aml;
    cudaGetSymbolAddress((void**)&xh,  g_xT_h);   cudaGetSymbolAddress((void**)&xl,  g_xT_l);
    cudaGetSymbolAddress((void**)&ih,  g_imgT_h); cudaGetSymbolAddress((void**)&il,  g_imgT_l);
    cudaGetSymbolAddress((void**)&wh,  g_w_h);    cudaGetSymbolAddress((void**)&wl,  g_w_l);
    cudaGetSymbolAddress((void**)&wch, g_wc_h);   cudaGetSymbolAddress((void**)&wcl, g_wc_l);
    cudaGetSymbolAddress((void**)&wth, g_wt_h);   cudaGetSymbolAddress((void**)&wtl, g_wt_l);
    cudaGetSymbolAddress((void**)&cth, g_ctxT_h); cudaGetSymbolAddress((void**)&ctl, g_ctxT_l);
    cudaGetSymbolAddress((void**)&sth, g_srcT_h); cudaGetSymbolAddress((void**)&stl, g_srcT_l);
    cudaGetSymbolAddress((void**)&tth, g_txtT_h); cudaGetSymbolAddress((void**)&ttl, g_txtT_l);
    cudaGetSymbolAddress((void**)&sh,  g_src_h);  cudaGetSymbolAddress((void**)&sl,  g_src_l);
    cudaGetSymbolAddress((void**)&amh, g_am_h);   cudaGetSymbolAddress((void**)&aml, g_am_l);

    cudaFuncSetAttribute(hgemm_kernel<0, 3>, cudaFuncAttributeMaxDynamicSharedMemorySize, HG_SMEM);
    cudaFuncSetAttribute(hgemm_kernel<0, 2>, cudaFuncAttributeMaxDynamicSharedMemorySize, HG_SMEM);
    cudaFuncSetAttribute(hgemm_kernel<2, 1>, cudaFuncAttributeMaxDynamicSharedMemorySize, HG_SMEM);
    cudaFuncSetAttribute(hgemm_kernel<5, 2>, cudaFuncAttributeMaxDynamicSharedMemorySize, HG_SMEM);
    cudaFuncSetAttribute(hgemm_kernel<6, 3>, cudaFuncAttributeMaxDynamicSharedMemorySize, HG_SMEM);
    cudaFuncSetAttribute(hgemm_kernel<7, 3>, cudaFuncAttributeMaxDynamicSharedMemorySize, HG_SMEM);

    const long long sSL  = (long long)IDF_ * LL;
    const long long sQI  = (long long)QQ * IDF_;
    const long long sLI  = (long long)LL * IDF_;
    const long long sLC  = (long long)LL * CDF_;
    const long long sQL  = (long long)QQ * LL;
    const long long sIQ  = (long long)IDF_ * QQ;

    // 1) xT split: x [b][i][q] -> [b][q][i] h/l
    split_tr_kernel<<<dim3(QQ / 32, IDF_ / 32, BB), dim3(32, 8)>>>(x, xh, xl, IDF_, QQ);
    // 2) ctxT split: context [b][c][l] -> [b][l][c] h/l
    split_tr_kernel<<<dim3(LL / 32, CDF_ / 32, BB), dim3(32, 8)>>>(context, cth, ctl, CDF_, LL);
    // 3) all three weight splits in one launch
    split_weights3_kernel<<<dim3(IDF_ * CDF_ / 512, 3), 256>>>(
        w_context, wch, wcl, w_text, wth, wtl, w_img, wh, wl);
    // 4) source = wc @ ctxT^T (3-term; feeds logits) -> h/l [i][l] + h/l [l][i]
    hgemm_kernel<6, 3><<<dim3(2, 4, BB), 256, HG_SMEM>>>(
        wch, wcl, cth, ctl, nullptr, sh, sl, sth, stl, IDF_, LL, CDF_, 0, sLC, sSL, sLI);
    // 5) text = tanh(wt @ ctxT^T) (3-term) -> transposed h/l [l][i] only
    hgemm_kernel<7, 3><<<dim3(2, 4, BB), 256, HG_SMEM>>>(
        wth, wtl, cth, ctl, nullptr, nullptr, nullptr, tth, ttl, IDF_, LL, CDF_, 0, sLC, 0, sLI);
    // 6) attn = xT @ srcT^T -> fp32 [b][q][l]  (3-term: softmax-critical)
    hgemm_kernel<0, 3><<<dim3(2, 32, BB), 256, HG_SMEM>>>(
        xh, xl, sth, stl, p_attn, nullptr, nullptr, nullptr, nullptr,
        QQ, LL, IDF_, sQI, sLI, sQL, 0);
    // 7-9) softmax over L (stores exp(p)); second-softmax sums -> rsums
    softmax_rows256<<<BB * QQ / 8, 256>>>(p_attn);
    sumexp_partial_kernel<<<dim3(BB, 16), 256>>>();
    sumexp_reduce_kernel<<<BB, 256>>>();
    // 10) imgT = tanh(xT @ w^T) -> h/l [b][q][o]  (1-term fp16: tanh-protected)
    hgemm_kernel<2, 1><<<dim3(4, 32, BB), 256, HG_SMEM>>>(
        xh, xl, wh, wl, nullptr, ih, il, nullptr, nullptr,
        QQ, IDF_, IDF_, sQI, 0, sQI, 0);
    // 11) combine GATED + fused transpose (2-term): v = tanh(.)*exp(p)*rsum
    //     -> am h/l [b][q][l] AND out_am fp32 [b][l][q]
    hgemm_kernel<5, 2><<<dim3(2, 32, BB), 256, HG_SMEM>>>(
        ih, il, tth, ttl, out_am, amh, aml, nullptr, nullptr,
        QQ, LL, IDF_, sQI, sLI, sQL, 0);
    // 12) wc = source @ am^T -> fp32 [b][i][q]  (2-term)
    hgemm_kernel<0, 2><<<dim3(32, 4, BB), 256, HG_SMEM>>>(
        sh, sl, amh, aml, out_wc, nullptr, nullptr, nullptr, nullptr,
        IDF_, QQ, LL, sSL, sQL, sIQ, 0);
}